// round 9
// baseline (speedup 1.0000x reference)
#include <cuda_runtime.h>
#include <cuda_bf16.h>
#include <math.h>
#include <stdint.h>

// ---------------- problem constants ----------------
#define BB 4
#define SS 2048
#define INF_DIM 64
#define DD 128
#define HID 400
#define HH 4
#define KK 20
#define NSEL 32
#define NA 18

#define NTOK 8192          // B*S
#define NTOK2 16384        // 2*B*S (true + sim)
#define NROW 32768         // B*H*S
#define KOFF ((size_t)NTOK * (HH * DD))   // offset of k rows inside g_qk

// output offsets (flattened tuple, C-order concat)
#define OFF_SCORE 0
#define OFF_Y     1
#define OFF_YPRED 32769
#define OFF_YLOW  65537
#define OFF_YHIGH 655361
#define OFF_ERR   1245185
#define OFF_QLOW  1253377
#define OFF_QHIGH 1843201
// total 2433025

__constant__ float c_alphas[NA] = {0.05f,0.06f,0.08f,0.1f,0.12f,0.14f,0.15f,0.17f,0.19f,
                                   0.2f,0.21f,0.23f,0.25f,0.3f,0.35f,0.38f,0.4f,0.45f};

// ---------------- scratch (static device allocations) ----------------
__device__ float g_h1[NTOK2 * HID];
__device__ float g_h2[NTOK2 * HID];
__device__ float g_enc[NTOK2 * DD];
__device__ float g_ln[NTOK2 * DD];
__device__ float g_qk[NTOK2 * (HH * DD)];
__device__ __nv_bfloat16 g_qb[(size_t)BB * HH * SS * DD];   // [bh][s][d]
__device__ __nv_bfloat16 g_kb[(size_t)BB * HH * SS * DD];
__device__ float g_scores[(size_t)BB * HH * SS * SS];       // 256 MB
__device__ float g_rowsq[NROW];

// ---------------- mma.sync helpers (compute_103-safe, sm_80 era PTX) ----------
__device__ __forceinline__ uint32_t smem_u32(const void* p) {
    uint32_t a;
    asm("{ .reg .u64 t; cvta.to.shared.u64 t, %1; cvt.u32.u64 %0, t; }" : "=r"(a) : "l"(p));
    return a;
}
__device__ __forceinline__ void ldsm_x4(uint32_t& r0, uint32_t& r1, uint32_t& r2, uint32_t& r3,
                                        uint32_t addr) {
    asm volatile("ldmatrix.sync.aligned.m8n8.x4.shared.b16 {%0,%1,%2,%3}, [%4];"
                 : "=r"(r0), "=r"(r1), "=r"(r2), "=r"(r3) : "r"(addr));
}
__device__ __forceinline__ void mma_bf16(float* c, const uint32_t* a, const uint32_t* b) {
    asm volatile("mma.sync.aligned.m16n8k16.row.col.f32.bf16.bf16.f32 "
                 "{%0,%1,%2,%3}, {%4,%5,%6,%7}, {%8,%9}, {%0,%1,%2,%3};"
                 : "+f"(c[0]), "+f"(c[1]), "+f"(c[2]), "+f"(c[3])
                 : "r"(a[0]), "r"(a[1]), "r"(a[2]), "r"(a[3]), "r"(b[0]), "r"(b[1]));
}

// swizzled offset within a 128row x 256B tile: row stride 256B, 16 chunks of 16B,
// XOR swizzle applied within each 128B half -> ldmatrix conflict-free.
__device__ __forceinline__ uint32_t tile_swz(int row, int ch) {
    return (uint32_t)row * 256u +
           (uint32_t)(((ch & 8) | ((ch ^ (row & 7)) & 7)) << 4);
}

// ---------------- generic SGEMM: C = act(A @ W + bias) (fp32) -----------------
__global__ __launch_bounds__(256) void sgemm_bias(
    const float* __restrict__ A, int lda,
    const float* __restrict__ W, int ldw,
    const float* __restrict__ bias,
    float* __restrict__ C, int ldc,
    int N, int K, int relu)
{
    __shared__ float As[2][8][128];
    __shared__ float Ws[2][8][128];
    const int tid = threadIdx.x;
    const int row0 = blockIdx.y * 128;
    const int col0 = blockIdx.x * 128;
    const int m0 = (tid >> 4) << 3;
    const int n0 = (tid & 15) << 3;
    const int ar = tid >> 1;
    const int ac = (tid & 1) << 2;
    const int wr = tid >> 5;
    const int wc = (tid & 31) << 2;
    const bool fullN = (col0 + 128 <= N);

    const float* Ap = A + (size_t)(row0 + ar) * lda + ac;

    float acc[8][8];
#pragma unroll
    for (int i = 0; i < 8; i++)
#pragma unroll
        for (int j = 0; j < 8; j++) acc[i][j] = 0.f;

    const int nk = K >> 3;
    float4 av = *reinterpret_cast<const float4*>(Ap);
    float4 wv;
    {
        const float* wp = W + (size_t)wr * ldw + col0 + wc;
        if (fullN) wv = *reinterpret_cast<const float4*>(wp);
        else {
            wv.x = (col0 + wc + 0 < N) ? wp[0] : 0.f;
            wv.y = (col0 + wc + 1 < N) ? wp[1] : 0.f;
            wv.z = (col0 + wc + 2 < N) ? wp[2] : 0.f;
            wv.w = (col0 + wc + 3 < N) ? wp[3] : 0.f;
        }
    }
    As[0][ac + 0][ar] = av.x; As[0][ac + 1][ar] = av.y;
    As[0][ac + 2][ar] = av.z; As[0][ac + 3][ar] = av.w;
    *reinterpret_cast<float4*>(&Ws[0][wr][wc]) = wv;
    __syncthreads();

    int buf = 0;
    for (int t = 0; t < nk; t++) {
        const bool more = (t + 1 < nk);
        if (more) {
            const int k0 = (t + 1) << 3;
            av = *reinterpret_cast<const float4*>(Ap + k0);
            const float* wp = W + (size_t)(k0 + wr) * ldw + col0 + wc;
            if (fullN) wv = *reinterpret_cast<const float4*>(wp);
            else {
                wv.x = (col0 + wc + 0 < N) ? wp[0] : 0.f;
                wv.y = (col0 + wc + 1 < N) ? wp[1] : 0.f;
                wv.z = (col0 + wc + 2 < N) ? wp[2] : 0.f;
                wv.w = (col0 + wc + 3 < N) ? wp[3] : 0.f;
            }
        }
#pragma unroll
        for (int kk = 0; kk < 8; kk++) {
            float4 a0 = *reinterpret_cast<const float4*>(&As[buf][kk][m0]);
            float4 a1 = *reinterpret_cast<const float4*>(&As[buf][kk][m0 + 4]);
            float4 w0 = *reinterpret_cast<const float4*>(&Ws[buf][kk][n0]);
            float4 w1 = *reinterpret_cast<const float4*>(&Ws[buf][kk][n0 + 4]);
            float a[8] = {a0.x, a0.y, a0.z, a0.w, a1.x, a1.y, a1.z, a1.w};
            float w[8] = {w0.x, w0.y, w0.z, w0.w, w1.x, w1.y, w1.z, w1.w};
#pragma unroll
            for (int i = 0; i < 8; i++)
#pragma unroll
                for (int j = 0; j < 8; j++) acc[i][j] = fmaf(a[i], w[j], acc[i][j]);
        }
        if (more) {
            const int nb = buf ^ 1;
            As[nb][ac + 0][ar] = av.x; As[nb][ac + 1][ar] = av.y;
            As[nb][ac + 2][ar] = av.z; As[nb][ac + 3][ar] = av.w;
            *reinterpret_cast<float4*>(&Ws[nb][wr][wc]) = wv;
            __syncthreads();
            buf = nb;
        }
    }

#pragma unroll
    for (int j = 0; j < 8; j++) {
        int c = col0 + n0 + j;
        if (c < N) {
            float bb = bias[c];
#pragma unroll
            for (int i = 0; i < 8; i++) {
                float v = acc[i][j] + bb;
                if (relu) v = fmaxf(v, 0.f);
                C[(size_t)(row0 + m0 + i) * ldc + c] = v;
            }
        }
    }
}

// ---------------- fp32 -> bf16 conversion, [b,s,h,d] -> [bh][s][d] ------------
__global__ __launch_bounds__(256) void cvt_bf16_kernel(const float* __restrict__ qk)
{
    int idx = blockIdx.x * 256 + threadIdx.x;     // < 1048576 (float4 groups)
    int d4 = idx & 31;
    int s  = (idx >> 5) & 2047;
    int bh = idx >> 16;
    int b = bh >> 2, h = bh & 3;
    size_t src = ((size_t)(b * SS + s)) * (HH * DD) + h * DD + d4 * 4;
    float4 q = *reinterpret_cast<const float4*>(qk + src);
    float4 k = *reinterpret_cast<const float4*>(qk + KOFF + src);
    __nv_bfloat162 q01 = __floats2bfloat162_rn(q.x, q.y);
    __nv_bfloat162 q23 = __floats2bfloat162_rn(q.z, q.w);
    __nv_bfloat162 k01 = __floats2bfloat162_rn(k.x, k.y);
    __nv_bfloat162 k23 = __floats2bfloat162_rn(k.z, k.w);
    uint2* qd = reinterpret_cast<uint2*>(g_qb) + idx;
    uint2* kd = reinterpret_cast<uint2*>(g_kb) + idx;
    *qd = make_uint2(*(uint32_t*)&q01, *(uint32_t*)&q23);
    *kd = make_uint2(*(uint32_t*)&k01, *(uint32_t*)&k23);
}

// ---------------- scores via mma.sync bf16 (fp32 accum) ----------------
// CTA tile 128x128, full K=128 in smem (no K loop). 8 warps, warp tile 64x32.
// smem: Q tile [0,32768), K tile [32768,65536). Row stride 256B (16 x 16B chunks),
// XOR swizzle within each 128B half (tile_swz).
__global__ __launch_bounds__(256, 2) void scores_mma_kernel()
{
    extern __shared__ char smem[];
    const uint32_t sb = smem_u32(smem);
    const int tid = threadIdx.x;
    const int bh = blockIdx.z;
    const int row0 = blockIdx.y * 128;
    const int col0 = blockIdx.x * 128;

    const __nv_bfloat16* qsrc = g_qb + (size_t)bh * SS * DD + (size_t)row0 * DD;
    const __nv_bfloat16* ksrc = g_kb + (size_t)bh * SS * DD + (size_t)col0 * DD;

    // load both 128x128 bf16 tiles (2048 16B-chunks each), swizzled
#pragma unroll
    for (int i = 0; i < 8; i++) {
        int idx = tid + i * 256;            // 0..2047
        int row = idx >> 4, ch = idx & 15;
        uint32_t off = tile_swz(row, ch);
        *reinterpret_cast<uint4*>(smem + off) =
            *reinterpret_cast<const uint4*>(qsrc + (size_t)row * DD + ch * 8);
        *reinterpret_cast<uint4*>(smem + 32768 + off) =
            *reinterpret_cast<const uint4*>(ksrc + (size_t)row * DD + ch * 8);
    }
    __syncthreads();

    const int wid = tid >> 5, lane = tid & 31;
    const int wm0 = (wid & 1) * 64;       // 2 m-warps
    const int wn0 = (wid >> 1) * 32;      // 4 n-warps

    float acc[4][4][4];
#pragma unroll
    for (int mf = 0; mf < 4; mf++)
#pragma unroll
        for (int nf = 0; nf < 4; nf++)
#pragma unroll
            for (int i = 0; i < 4; i++) acc[mf][nf][i] = 0.f;

    // A fragment rows: lanes 0-15 -> rows m0..m15 (k chunk 2s), lanes 16-31 same rows (k chunk 2s+1)
    uint32_t abase[4]; int ax[4];
#pragma unroll
    for (int mf = 0; mf < 4; mf++) {
        int r = wm0 + mf * 16 + (lane & 15);
        abase[mf] = sb + (uint32_t)r * 256u;
        ax[mf] = r & 7;
    }
    const int alb = lane >> 4;
    // B fragment rows: lanes {0-7,8-15,16-23,24-31} -> {n0-7 k-lo, n0-7 k-hi, n8-15 k-lo, n8-15 k-hi}
    uint32_t bbase[2]; int bx[2];
#pragma unroll
    for (int nf2 = 0; nf2 < 2; nf2++) {
        int r = wn0 + nf2 * 16 + (lane & 7) + ((lane & 16) >> 1);
        bbase[nf2] = sb + 32768u + (uint32_t)r * 256u;
        bx[nf2] = r & 7;
    }
    const int blb = (lane >> 3) & 1;

#pragma unroll
    for (int s = 0; s < 8; s++) {
        uint32_t a[4][4], b[4][2];
        const int ca = 2 * s + alb;
        const int cb = 2 * s + blb;
#pragma unroll
        for (int mf = 0; mf < 4; mf++)
            ldsm_x4(a[mf][0], a[mf][1], a[mf][2], a[mf][3],
                    abase[mf] + (uint32_t)(((ca & 8) | ((ca ^ ax[mf]) & 7)) << 4));
#pragma unroll
        for (int nf2 = 0; nf2 < 2; nf2++) {
            uint32_t r0, r1, r2, r3;
            ldsm_x4(r0, r1, r2, r3,
                    bbase[nf2] + (uint32_t)(((cb & 8) | ((cb ^ bx[nf2]) & 7)) << 4));
            b[nf2 * 2][0] = r0; b[nf2 * 2][1] = r1;
            b[nf2 * 2 + 1][0] = r2; b[nf2 * 2 + 1][1] = r3;
        }
#pragma unroll
        for (int mf = 0; mf < 4; mf++)
#pragma unroll
            for (int nf = 0; nf < 4; nf++)
                mma_bf16(acc[mf][nf], a[mf], b[nf]);
    }

    // epilogue: scale, diag=-inf, float2 stores
    const float scale = 0.08838834764831845f;   // 1/sqrt(128)
    const float ninf = __int_as_float(0xff800000);
    float* C = g_scores + (size_t)bh * SS * SS;
    const int qr = lane >> 2, qc = (lane & 3) * 2;
#pragma unroll
    for (int mf = 0; mf < 4; mf++) {
        int r1 = row0 + wm0 + mf * 16 + qr;
        int r2 = r1 + 8;
#pragma unroll
        for (int nf = 0; nf < 4; nf++) {
            int c = col0 + wn0 + nf * 8 + qc;
            float2 v1, v2;
            v1.x = (r1 == c)     ? ninf : acc[mf][nf][0] * scale;
            v1.y = (r1 == c + 1) ? ninf : acc[mf][nf][1] * scale;
            v2.x = (r2 == c)     ? ninf : acc[mf][nf][2] * scale;
            v2.y = (r2 == c + 1) ? ninf : acc[mf][nf][3] * scale;
            *reinterpret_cast<float2*>(C + (size_t)r1 * SS + c) = v1;
            *reinterpret_cast<float2*>(C + (size_t)r2 * SS + c) = v2;
        }
    }
}

// ---------------- LayerNorm (warp per row) ----------------
__global__ __launch_bounds__(256) void ln_kernel(
    const float* __restrict__ gq, const float* __restrict__ bq,
    const float* __restrict__ gk, const float* __restrict__ bk)
{
    const int warp = threadIdx.x >> 5, lane = threadIdx.x & 31;
    const int row = blockIdx.x * 8 + warp;
    const float* x = g_enc + (size_t)row * DD;
    float v0 = x[lane], v1 = x[lane + 32], v2 = x[lane + 64], v3 = x[lane + 96];
    float s = v0 + v1 + v2 + v3;
#pragma unroll
    for (int o = 16; o; o >>= 1) s += __shfl_xor_sync(0xffffffffu, s, o);
    float mu = s * (1.f / 128.f);
    float d0 = v0 - mu, d1 = v1 - mu, d2 = v2 - mu, d3 = v3 - mu;
    float sq = d0 * d0 + d1 * d1 + d2 * d2 + d3 * d3;
#pragma unroll
    for (int o = 16; o; o >>= 1) sq += __shfl_xor_sync(0xffffffffu, sq, o);
    float rs = rsqrtf(sq * (1.f / 128.f) + 1e-5f);
    const float* g = (row < NTOK) ? gq : gk;
    const float* be = (row < NTOK) ? bq : bk;
    float* o = g_ln + (size_t)row * DD;
    o[lane]      = d0 * rs * g[lane]      + be[lane];
    o[lane + 32] = d1 * rs * g[lane + 32] + be[lane + 32];
    o[lane + 64] = d2 * rs * g[lane + 64] + be[lane + 64];
    o[lane + 96] = d3 * rs * g[lane + 96] + be[lane + 96];
}

// ---------------- top-NSEL (bf16 scores) -> exact rescore -> top-20 -> quantiles
__global__ __launch_bounds__(128) void topk_quantile_kernel(
    const float* __restrict__ qk,
    const float* __restrict__ errors,
    const float* __restrict__ y,
    const float* __restrict__ y_pred,
    float* __restrict__ out)
{
    __shared__ float s_v[4][NSEL * 32];
    __shared__ int   s_i[4][NSEL * 32];
    __shared__ float s_q[4][DD];
    __shared__ float s_sorted[4][KK];

    const int warp = threadIdx.x >> 5, lane = threadIdx.x & 31;
    const int row = blockIdx.x * 4 + warp;           // < 32768
    const int b = row >> 13;
    const int h = (row >> 11) & 3;
    const int s = row & 2047;
    const float* sr = g_scores + (size_t)row * SS;
    const float ninf = __int_as_float(0xff800000);

#pragma unroll
    for (int t = 0; t < NSEL; t++) s_v[warp][t * 32 + lane] = ninf;

    // per-lane streaming insertion top-32 of bf16-accurate scores
    for (int j = 0; j < SS / 32; j++) {
        int m = j * 32 + lane;
        float x = sr[m];
        if (x > s_v[warp][(NSEL - 1) * 32 + lane]) {
            int t = NSEL - 1;
            while (t > 0 && s_v[warp][(t - 1) * 32 + lane] < x) {
                s_v[warp][t * 32 + lane] = s_v[warp][(t - 1) * 32 + lane];
                s_i[warp][t * 32 + lane] = s_i[warp][(t - 1) * 32 + lane];
                t--;
            }
            s_v[warp][t * 32 + lane] = x;
            s_i[warp][t * 32 + lane] = m;
        }
    }
    __syncwarp();

    // 32-round merge via warp argmax -> lane r holds r-th best index
    int p = 0;
    int my_m = 0;
    for (int r = 0; r < NSEL; r++) {
        float cand = (p < NSEL) ? s_v[warp][p * 32 + lane] : ninf;
        float bv = cand; int bl = lane;
#pragma unroll
        for (int off = 16; off; off >>= 1) {
            float ov = __shfl_down_sync(0xffffffffu, bv, off);
            int   ol = __shfl_down_sync(0xffffffffu, bl, off);
            if (ov > bv) { bv = ov; bl = ol; }
        }
        bl = __shfl_sync(0xffffffffu, bl, 0);
        int mi = (lane == bl && p < NSEL) ? s_i[warp][p * 32 + lane] : 0;
        mi = __shfl_sync(0xffffffffu, mi, bl);
        if (lane == bl) p++;
        if (lane == r) my_m = mi;
    }

    // ---- exact fp32 rescore of the 32 candidates ----
    const float* qrow = qk + ((size_t)(b * SS + s)) * (HH * DD) + h * DD;
    *reinterpret_cast<float4*>(&s_q[warp][lane * 4]) =
        *reinterpret_cast<const float4*>(qrow + lane * 4);
    __syncwarp();
    const float* krow = qk + KOFF + ((size_t)(b * SS + my_m)) * (HH * DD) + h * DD;
    float ex = 0.f;
#pragma unroll
    for (int d4 = 0; d4 < 32; d4++) {
        float4 kv = *reinterpret_cast<const float4*>(krow + d4 * 4);
        float4 qv = *reinterpret_cast<const float4*>(&s_q[warp][d4 * 4]);
        ex = fmaf(qv.x, kv.x, ex);
        ex = fmaf(qv.y, kv.y, ex);
        ex = fmaf(qv.z, kv.z, ex);
        ex = fmaf(qv.w, kv.w, ex);
    }

    // rank among 32 by (exact score desc, index asc)
    int rank_sel = 0;
#pragma unroll
    for (int j = 0; j < NSEL; j++) {
        float sj = __shfl_sync(0xffffffffu, ex, j);
        int   mj = __shfl_sync(0xffffffffu, my_m, j);
        if ((sj > ex) || (sj == ex && mj < my_m)) rank_sel++;
    }
    const bool selected = (rank_sel < KK);

    // gather error values for the selected 20
    float e = selected ? errors[((size_t)(b * SS + my_m)) * 4 + 0] : 0.f;

    // sort the 20 selected error values (ascending)
    int rank_e = 0;
#pragma unroll
    for (int j = 0; j < NSEL; j++) {
        float ej  = __shfl_sync(0xffffffffu, e, j);
        int   rsj = __shfl_sync(0xffffffffu, rank_sel, j);
        if (selected && rsj < KK && ((ej < e) || (ej == e && rsj < rank_sel))) rank_e++;
    }
    if (selected) s_sorted[warp][rank_e] = e;
    __syncwarp();

    const float yp = y_pred[((size_t)(b * SS + s)) * 4 + 0];
    float ql = 0.f, qh = 0.f;
    if (lane < NA) {
        float alpha = c_alphas[lane];
        float pl = 0.5f * alpha * (float)(KK - 1);
        int il = (int)pl; float fl = pl - (float)il;
        ql = s_sorted[warp][il] + fl * (s_sorted[warp][il + 1] - s_sorted[warp][il]);
        float ph = (1.f - 0.5f * alpha) * (float)(KK - 1);
        int ih = (int)ph; float fh = ph - (float)ih;
        qh = s_sorted[warp][ih] + fh * (s_sorted[warp][ih + 1] - s_sorted[warp][ih]);
        size_t oidx = ((size_t)((h * BB + b) * NA + lane)) * SS + s;
        out[OFF_QLOW  + oidx] = ql;
        out[OFF_QHIGH + oidx] = qh;
        out[OFF_YLOW  + oidx] = ql + yp;
        out[OFF_YHIGH + oidx] = qh + yp;
    }

    float t = ql + qh;
#pragma unroll
    for (int o = 16; o; o >>= 1) t += __shfl_down_sync(0xffffffffu, t, o);
    if (lane == 0) {
        float me = t * (1.f / 36.f);
        float yt = y[((size_t)(b * SS + s)) * 4 + 0];
        float d = yt - (me + yp);
        g_rowsq[row] = d * d;
    }
}

// ---------------- passthrough copies ----------------
__global__ void copy_kernel(const float* __restrict__ y,
                            const float* __restrict__ yp,
                            const float* __restrict__ err,
                            float* __restrict__ out)
{
    int i = blockIdx.x * blockDim.x + threadIdx.x;
    if (i < 32768) out[OFF_Y + i] = y[i];
    else if (i < 65536) out[OFF_YPRED + (i - 32768)] = yp[i - 32768];
    else if (i < 73728) { int j = i - 65536; out[OFF_ERR + j] = err[(size_t)j * 4]; }
}

// ---------------- final scalar reduce ----------------
__global__ void reduce_kernel(float* __restrict__ out)
{
    __shared__ float sh[1024];
    float s = 0.f;
    for (int i = threadIdx.x; i < NROW; i += 1024) s += g_rowsq[i];
    sh[threadIdx.x] = s;
    __syncthreads();
    for (int o = 512; o; o >>= 1) {
        if (threadIdx.x < o) sh[threadIdx.x] += sh[threadIdx.x + o];
        __syncthreads();
    }
    if (threadIdx.x == 0) out[OFF_SCORE] = sh[0] * (1.f / (float)NROW);
}

// ---------------- launch ----------------
extern "C" void kernel_launch(void* const* d_in, const int* in_sizes, int n_in,
                              void* d_out, int out_size)
{
    const float* Xt   = (const float*)d_in[0];
    const float* Xs   = (const float*)d_in[1];
    const float* err  = (const float*)d_in[2];
    const float* y    = (const float*)d_in[3];
    const float* ypr  = (const float*)d_in[4];
    const float* W1   = (const float*)d_in[5];
    const float* b1   = (const float*)d_in[6];
    const float* W2   = (const float*)d_in[7];
    const float* b2   = (const float*)d_in[8];
    const float* W3   = (const float*)d_in[9];
    const float* b3   = (const float*)d_in[10];
    const float* W4   = (const float*)d_in[11];
    const float* b4   = (const float*)d_in[12];
    const float* Wq   = (const float*)d_in[13];
    const float* bq   = (const float*)d_in[14];
    const float* Wk   = (const float*)d_in[15];
    const float* bk   = (const float*)d_in[16];
    const float* gq   = (const float*)d_in[17];
    const float* betaq= (const float*)d_in[18];
    const float* gk   = (const float*)d_in[19];
    const float* betak= (const float*)d_in[20];
    float* out = (float*)d_out;

    float *p_h1, *p_h2, *p_enc, *p_ln, *p_qk;
    cudaGetSymbolAddress((void**)&p_h1, g_h1);
    cudaGetSymbolAddress((void**)&p_h2, g_h2);
    cudaGetSymbolAddress((void**)&p_enc, g_enc);
    cudaGetSymbolAddress((void**)&p_ln, g_ln);
    cudaGetSymbolAddress((void**)&p_qk, g_qk);

    cudaFuncSetAttribute(scores_mma_kernel,
                         cudaFuncAttributeMaxDynamicSharedMemorySize, 65536);

    // MLP layer 1 (true rows [0,8192), sim rows [8192,16384))
    sgemm_bias<<<dim3(4, 64), 256>>>(Xt, INF_DIM, W1, HID, b1, p_h1, HID, HID, INF_DIM, 1);
    sgemm_bias<<<dim3(4, 64), 256>>>(Xs, INF_DIM, W1, HID, b1, p_h1 + (size_t)NTOK * HID, HID, HID, INF_DIM, 1);
    // layers 2,3
    sgemm_bias<<<dim3(4, 128), 256>>>(p_h1, HID, W2, HID, b2, p_h2, HID, HID, HID, 1);
    sgemm_bias<<<dim3(4, 128), 256>>>(p_h2, HID, W3, HID, b3, p_h1, HID, HID, HID, 1);
    // layer 4 (no relu) -> enc
    sgemm_bias<<<dim3(1, 128), 256>>>(p_h1, HID, W4, DD, b4, p_enc, DD, DD, HID, 0);
    // layernorm
    ln_kernel<<<NTOK2 / 8, 256>>>(gq, betaq, gk, betak);
    // projections
    sgemm_bias<<<dim3(4, 64), 256>>>(p_ln, DD, Wq, HH * DD, bq, p_qk, HH * DD, HH * DD, DD, 0);
    sgemm_bias<<<dim3(4, 64), 256>>>(p_ln + (size_t)NTOK * DD, DD, Wk, HH * DD, bk,
                                     p_qk + KOFF, HH * DD, HH * DD, DD, 0);
    // bf16 conversion for tensor-core scores
    cvt_bf16_kernel<<<4096, 256>>>(p_qk);
    // scores via mma.sync bf16 (fp32 accumulate)
    scores_mma_kernel<<<dim3(16, 16, 16), 256, 65536>>>();
    // top-32 (bf16) -> exact fp32 rescore -> top-20 -> quantiles
    topk_quantile_kernel<<<NROW / 4, 128>>>(p_qk, err, y, ypr, out);
    // passthrough copies
    copy_kernel<<<288, 256>>>(y, ypr, err, out);
    // scalar score
    reduce_kernel<<<1, 1024>>>(out);
}

// round 11
// speedup vs baseline: 1.1344x; 1.1344x over previous
#include <cuda_runtime.h>
#include <cuda_bf16.h>
#include <math.h>
#include <stdint.h>

// ---------------- problem constants ----------------
#define BB 4
#define SS 2048
#define INF_DIM 64
#define DD 128
#define HID 400
#define HH 4
#define KK 20
#define NSEL 32
#define NA 18

#define NTOK 8192          // B*S
#define NTOK2 16384        // 2*B*S (true + sim)
#define NROW 32768         // B*H*S
#define KOFF ((size_t)NTOK * (HH * DD))   // offset of k rows inside g_qk

// output offsets (flattened tuple, C-order concat)
#define OFF_SCORE 0
#define OFF_Y     1
#define OFF_YPRED 32769
#define OFF_YLOW  65537
#define OFF_YHIGH 655361
#define OFF_ERR   1245185
#define OFF_QLOW  1253377
#define OFF_QHIGH 1843201
// total 2433025

__constant__ float c_alphas[NA] = {0.05f,0.06f,0.08f,0.1f,0.12f,0.14f,0.15f,0.17f,0.19f,
                                   0.2f,0.21f,0.23f,0.25f,0.3f,0.35f,0.38f,0.4f,0.45f};

// ---------------- scratch (static device allocations) ----------------
__device__ float g_h1[NTOK2 * HID];
__device__ float g_h2[NTOK2 * HID];
__device__ float g_enc[NTOK2 * DD];
__device__ float g_ln[NTOK2 * DD];
__device__ float g_qk[NTOK2 * (HH * DD)];
__device__ __nv_bfloat16 g_qb[(size_t)BB * HH * SS * DD];   // [bh][s][d]
__device__ __nv_bfloat16 g_kb[(size_t)BB * HH * SS * DD];
__device__ float g_rowsq[NROW];

// ---------------- mma.sync helpers (compute_103-safe, sm_80 era PTX) ----------
__device__ __forceinline__ uint32_t smem_u32(const void* p) {
    uint32_t a;
    asm("{ .reg .u64 t; cvta.to.shared.u64 t, %1; cvt.u32.u64 %0, t; }" : "=r"(a) : "l"(p));
    return a;
}
__device__ __forceinline__ void ldsm_x4(uint32_t& r0, uint32_t& r1, uint32_t& r2, uint32_t& r3,
                                        uint32_t addr) {
    asm volatile("ldmatrix.sync.aligned.m8n8.x4.shared.b16 {%0,%1,%2,%3}, [%4];"
                 : "=r"(r0), "=r"(r1), "=r"(r2), "=r"(r3) : "r"(addr));
}
__device__ __forceinline__ void mma_bf16(float* c, const uint32_t* a, const uint32_t* b) {
    asm volatile("mma.sync.aligned.m16n8k16.row.col.f32.bf16.bf16.f32 "
                 "{%0,%1,%2,%3}, {%4,%5,%6,%7}, {%8,%9}, {%0,%1,%2,%3};"
                 : "+f"(c[0]), "+f"(c[1]), "+f"(c[2]), "+f"(c[3])
                 : "r"(a[0]), "r"(a[1]), "r"(a[2]), "r"(a[3]), "r"(b[0]), "r"(b[1]));
}

// swizzled offset within a 128row x 256B tile: row stride 256B, 16 chunks of 16B,
// XOR swizzle applied within each 128B half -> ldmatrix conflict-free.
__device__ __forceinline__ uint32_t tile_swz(int row, int ch) {
    return (uint32_t)row * 256u +
           (uint32_t)(((ch & 8) | ((ch ^ (row & 7)) & 7)) << 4);
}

// ---------------- generic SGEMM: C = act(A @ W + bias) (fp32) -----------------
__global__ __launch_bounds__(256) void sgemm_bias(
    const float* __restrict__ A, int lda,
    const float* __restrict__ W, int ldw,
    const float* __restrict__ bias,
    float* __restrict__ C, int ldc,
    int N, int K, int relu)
{
    __shared__ float As[2][8][128];
    __shared__ float Ws[2][8][128];
    const int tid = threadIdx.x;
    const int row0 = blockIdx.y * 128;
    const int col0 = blockIdx.x * 128;
    const int m0 = (tid >> 4) << 3;
    const int n0 = (tid & 15) << 3;
    const int ar = tid >> 1;
    const int ac = (tid & 1) << 2;
    const int wr = tid >> 5;
    const int wc = (tid & 31) << 2;
    const bool fullN = (col0 + 128 <= N);

    const float* Ap = A + (size_t)(row0 + ar) * lda + ac;

    float acc[8][8];
#pragma unroll
    for (int i = 0; i < 8; i++)
#pragma unroll
        for (int j = 0; j < 8; j++) acc[i][j] = 0.f;

    const int nk = K >> 3;
    float4 av = *reinterpret_cast<const float4*>(Ap);
    float4 wv;
    {
        const float* wp = W + (size_t)wr * ldw + col0 + wc;
        if (fullN) wv = *reinterpret_cast<const float4*>(wp);
        else {
            wv.x = (col0 + wc + 0 < N) ? wp[0] : 0.f;
            wv.y = (col0 + wc + 1 < N) ? wp[1] : 0.f;
            wv.z = (col0 + wc + 2 < N) ? wp[2] : 0.f;
            wv.w = (col0 + wc + 3 < N) ? wp[3] : 0.f;
        }
    }
    As[0][ac + 0][ar] = av.x; As[0][ac + 1][ar] = av.y;
    As[0][ac + 2][ar] = av.z; As[0][ac + 3][ar] = av.w;
    *reinterpret_cast<float4*>(&Ws[0][wr][wc]) = wv;
    __syncthreads();

    int buf = 0;
    for (int t = 0; t < nk; t++) {
        const bool more = (t + 1 < nk);
        if (more) {
            const int k0 = (t + 1) << 3;
            av = *reinterpret_cast<const float4*>(Ap + k0);
            const float* wp = W + (size_t)(k0 + wr) * ldw + col0 + wc;
            if (fullN) wv = *reinterpret_cast<const float4*>(wp);
            else {
                wv.x = (col0 + wc + 0 < N) ? wp[0] : 0.f;
                wv.y = (col0 + wc + 1 < N) ? wp[1] : 0.f;
                wv.z = (col0 + wc + 2 < N) ? wp[2] : 0.f;
                wv.w = (col0 + wc + 3 < N) ? wp[3] : 0.f;
            }
        }
#pragma unroll
        for (int kk = 0; kk < 8; kk++) {
            float4 a0 = *reinterpret_cast<const float4*>(&As[buf][kk][m0]);
            float4 a1 = *reinterpret_cast<const float4*>(&As[buf][kk][m0 + 4]);
            float4 w0 = *reinterpret_cast<const float4*>(&Ws[buf][kk][n0]);
            float4 w1 = *reinterpret_cast<const float4*>(&Ws[buf][kk][n0 + 4]);
            float a[8] = {a0.x, a0.y, a0.z, a0.w, a1.x, a1.y, a1.z, a1.w};
            float w[8] = {w0.x, w0.y, w0.z, w0.w, w1.x, w1.y, w1.z, w1.w};
#pragma unroll
            for (int i = 0; i < 8; i++)
#pragma unroll
                for (int j = 0; j < 8; j++) acc[i][j] = fmaf(a[i], w[j], acc[i][j]);
        }
        if (more) {
            const int nb = buf ^ 1;
            As[nb][ac + 0][ar] = av.x; As[nb][ac + 1][ar] = av.y;
            As[nb][ac + 2][ar] = av.z; As[nb][ac + 3][ar] = av.w;
            *reinterpret_cast<float4*>(&Ws[nb][wr][wc]) = wv;
            __syncthreads();
            buf = nb;
        }
    }

#pragma unroll
    for (int j = 0; j < 8; j++) {
        int c = col0 + n0 + j;
        if (c < N) {
            float bb = bias[c];
#pragma unroll
            for (int i = 0; i < 8; i++) {
                float v = acc[i][j] + bb;
                if (relu) v = fmaxf(v, 0.f);
                C[(size_t)(row0 + m0 + i) * ldc + c] = v;
            }
        }
    }
}

// ---------------- fp32 -> bf16 conversion, [b,s,h,d] -> [bh][s][d] ------------
__global__ __launch_bounds__(256) void cvt_bf16_kernel(const float* __restrict__ qk)
{
    int idx = blockIdx.x * 256 + threadIdx.x;     // < 1048576 (float4 groups)
    int d4 = idx & 31;
    int s  = (idx >> 5) & 2047;
    int bh = idx >> 16;
    int b = bh >> 2, h = bh & 3;
    size_t src = ((size_t)(b * SS + s)) * (HH * DD) + h * DD + d4 * 4;
    float4 q = *reinterpret_cast<const float4*>(qk + src);
    float4 k = *reinterpret_cast<const float4*>(qk + KOFF + src);
    __nv_bfloat162 q01 = __floats2bfloat162_rn(q.x, q.y);
    __nv_bfloat162 q23 = __floats2bfloat162_rn(q.z, q.w);
    __nv_bfloat162 k01 = __floats2bfloat162_rn(k.x, k.y);
    __nv_bfloat162 k23 = __floats2bfloat162_rn(k.z, k.w);
    uint2* qd = reinterpret_cast<uint2*>(g_qb) + idx;
    uint2* kd = reinterpret_cast<uint2*>(g_kb) + idx;
    *qd = make_uint2(*(uint32_t*)&q01, *(uint32_t*)&q23);
    *kd = make_uint2(*(uint32_t*)&k01, *(uint32_t*)&k23);
}

// ---------------- fused scores MMA + top-32 + exact rescore + quantiles -------
// grid (16 row-tiles, 16 bh), 512 threads (16 warps, 32x32 warp tiles).
// smem layout (dynamic):
#define SM_QT   0          // Q bf16 tile, 32768 B (swizzled, 256B row stride)
#define SM_KT   32768      // K bf16 tile, 32768 B
#define SM_SC   65536      // scores f32 [128][132] = 67584 B
#define SM_RTV  133120     // rowtop values f32 [128][32] = 16384 B
#define SM_RTI  149504     // rowtop indices i32 [128][32] = 16384 B
#define SM_QF   165888     // per-warp q fp32 row [16][128] = 8192 B
#define SM_SRT  174080     // per-warp sorted errs [16][20] = 1280 B
#define SM_FUSED_TOTAL 175360

__global__ __launch_bounds__(512, 1) void fused_scores_topk(
    const float* __restrict__ qk,
    const float* __restrict__ errors,
    const float* __restrict__ y,
    const float* __restrict__ y_pred,
    float* __restrict__ out)
{
    extern __shared__ char smem[];
    const uint32_t sb = smem_u32(smem);
    float* sc  = reinterpret_cast<float*>(smem + SM_SC);
    float* rtv = reinterpret_cast<float*>(smem + SM_RTV);
    int*   rti = reinterpret_cast<int*>(smem + SM_RTI);
    float* qf  = reinterpret_cast<float*>(smem + SM_QF);
    float* srt = reinterpret_cast<float*>(smem + SM_SRT);

    const int tid = threadIdx.x;
    const int wid = tid >> 5, lane = tid & 31;
    const int rt0 = blockIdx.x * 128;     // q row tile base
    const int bh = blockIdx.y;
    const int b = bh >> 2, h = bh & 3;
    const float ninf = __int_as_float(0xff800000);

    // init per-row top-32 lists
    for (int i = tid; i < 128 * 32; i += 512) { rtv[i] = ninf; rti[i] = 0; }

    // load Q tile (swizzled)
    const __nv_bfloat16* qsrc = g_qb + ((size_t)bh * SS + rt0) * DD;
#pragma unroll
    for (int i = 0; i < 4; i++) {
        int idx = tid + i * 512;          // 0..2047
        int row = idx >> 4, ch = idx & 15;
        *reinterpret_cast<uint4*>(smem + SM_QT + tile_swz(row, ch)) =
            *reinterpret_cast<const uint4*>(qsrc + (size_t)row * DD + ch * 8);
    }

    const int wm0 = (wid & 3) * 32;       // 4 m-warps
    const int wn0 = (wid >> 2) * 32;      // 4 n-warps

    // A fragment bases
    uint32_t abase[2]; int ax[2];
#pragma unroll
    for (int mf = 0; mf < 2; mf++) {
        int r = wm0 + mf * 16 + (lane & 15);
        abase[mf] = sb + SM_QT + (uint32_t)r * 256u;
        ax[mf] = r & 7;
    }
    const int alb = lane >> 4;
    // B fragment bases
    uint32_t bbase[2]; int bx[2];
#pragma unroll
    for (int nf2 = 0; nf2 < 2; nf2++) {
        int r = wn0 + nf2 * 16 + (lane & 7) + ((lane & 16) >> 1);
        bbase[nf2] = sb + SM_KT + (uint32_t)r * 256u;
        bx[nf2] = r & 7;
    }
    const int blb = (lane >> 3) & 1;

    const float scale = 0.08838834764831845f;   // 1/sqrt(128)

    for (int ct = 0; ct < 16; ct++) {
        __syncthreads();   // sc/Kt consumed by previous iteration
        // load K tile (rows ct*128..+127)
        const __nv_bfloat16* ksrc = g_kb + ((size_t)bh * SS + ct * 128) * DD;
#pragma unroll
        for (int i = 0; i < 4; i++) {
            int idx = tid + i * 512;
            int row = idx >> 4, ch = idx & 15;
            *reinterpret_cast<uint4*>(smem + SM_KT + tile_swz(row, ch)) =
                *reinterpret_cast<const uint4*>(ksrc + (size_t)row * DD + ch * 8);
        }
        __syncthreads();

        float acc[2][4][4];
#pragma unroll
        for (int mf = 0; mf < 2; mf++)
#pragma unroll
            for (int nf = 0; nf < 4; nf++)
#pragma unroll
                for (int i = 0; i < 4; i++) acc[mf][nf][i] = 0.f;

#pragma unroll
        for (int s = 0; s < 8; s++) {
            uint32_t a[2][4], bfr[4][2];
            const int ca = 2 * s + alb;
            const int cb = 2 * s + blb;
#pragma unroll
            for (int mf = 0; mf < 2; mf++)
                ldsm_x4(a[mf][0], a[mf][1], a[mf][2], a[mf][3],
                        abase[mf] + (uint32_t)(((ca & 8) | ((ca ^ ax[mf]) & 7)) << 4));
#pragma unroll
            for (int nf2 = 0; nf2 < 2; nf2++) {
                uint32_t r0, r1, r2, r3;
                ldsm_x4(r0, r1, r2, r3,
                        bbase[nf2] + (uint32_t)(((cb & 8) | ((cb ^ bx[nf2]) & 7)) << 4));
                bfr[nf2 * 2][0] = r0; bfr[nf2 * 2][1] = r1;
                bfr[nf2 * 2 + 1][0] = r2; bfr[nf2 * 2 + 1][1] = r3;
            }
#pragma unroll
            for (int mf = 0; mf < 2; mf++)
#pragma unroll
                for (int nf = 0; nf < 4; nf++)
                    mma_bf16(acc[mf][nf], a[mf], bfr[nf]);
        }

        // epilogue: scaled scores (diag-masked) -> smem sc
        const int qr = lane >> 2, qc = (lane & 3) * 2;
#pragma unroll
        for (int mf = 0; mf < 2; mf++) {
            int r1 = wm0 + mf * 16 + qr;
            int r2 = r1 + 8;
            int gr1 = rt0 + r1, gr2 = rt0 + r2;
#pragma unroll
            for (int nf = 0; nf < 4; nf++) {
                int cl = wn0 + nf * 8 + qc;
                int gc = ct * 128 + cl;
                float2 v1, v2;
                v1.x = (gr1 == gc)     ? ninf : acc[mf][nf][0] * scale;
                v1.y = (gr1 == gc + 1) ? ninf : acc[mf][nf][1] * scale;
                v2.x = (gr2 == gc)     ? ninf : acc[mf][nf][2] * scale;
                v2.y = (gr2 == gc + 1) ? ninf : acc[mf][nf][3] * scale;
                *reinterpret_cast<float2*>(&sc[r1 * 132 + cl]) = v1;
                *reinterpret_cast<float2*>(&sc[r2 * 132 + cl]) = v2;
            }
        }
        __syncthreads();

        // top-32 streaming update: warp handles rows wid*8 .. wid*8+7
#pragma unroll 1
        for (int rr = 0; rr < 8; rr++) {
            const int r = wid * 8 + rr;
            float* rv = &rtv[r * 32];
            int*   ri = &rti[r * 32];
#pragma unroll
            for (int j = 0; j < 4; j++) {
                float x = sc[r * 132 + lane + 32 * j];
                int c = ct * 128 + lane + 32 * j;
                bool pend = x > rv[31];
                unsigned m = __ballot_sync(0xffffffffu, pend);
                while (m) {
                    int ld = __ffs(m) - 1;
                    if (lane == ld) {
                        if (x > rv[31]) {
                            int t = 31;
                            while (t > 0 && rv[t - 1] < x) {
                                rv[t] = rv[t - 1]; ri[t] = ri[t - 1]; t--;
                            }
                            rv[t] = x; ri[t] = c;
                        }
                    }
                    __syncwarp();
                    m &= m - 1;
                }
            }
        }
    }
    __syncthreads();

    // ---- exact fp32 rescore + quantiles: warp per row, 8 rows serial ----
#pragma unroll 1
    for (int rr = 0; rr < 8; rr++) {
        const int r = wid * 8 + rr;
        const int sgl = rt0 + r;                        // s index in [0,2048)
        // stage q fp32 row for broadcast
        const float* qrow = qk + ((size_t)(b * SS + sgl)) * (HH * DD) + h * DD;
        *reinterpret_cast<float4*>(&qf[wid * 128 + lane * 4]) =
            *reinterpret_cast<const float4*>(qrow + lane * 4);
        __syncwarp();

        const int my_m = rti[r * 32 + lane];
        const float* krow = qk + KOFF + ((size_t)(b * SS + my_m)) * (HH * DD) + h * DD;
        float ex = 0.f;
#pragma unroll
        for (int d4 = 0; d4 < 32; d4++) {
            float4 kv = *reinterpret_cast<const float4*>(krow + d4 * 4);
            float4 qv = *reinterpret_cast<const float4*>(&qf[wid * 128 + d4 * 4]);
            ex = fmaf(qv.x, kv.x, ex);
            ex = fmaf(qv.y, kv.y, ex);
            ex = fmaf(qv.z, kv.z, ex);
            ex = fmaf(qv.w, kv.w, ex);
        }

        // rank among 32 by (exact score desc, index asc)
        int rank_sel = 0;
#pragma unroll
        for (int j = 0; j < NSEL; j++) {
            float sj = __shfl_sync(0xffffffffu, ex, j);
            int   mj = __shfl_sync(0xffffffffu, my_m, j);
            if ((sj > ex) || (sj == ex && mj < my_m)) rank_sel++;
        }
        const bool selected = (rank_sel < KK);

        float e = selected ? errors[((size_t)(b * SS + my_m)) * 4 + 0] : 0.f;

        // sort the 20 selected error values (ascending)
        int rank_e = 0;
#pragma unroll
        for (int j = 0; j < NSEL; j++) {
            float ej  = __shfl_sync(0xffffffffu, e, j);
            int   rsj = __shfl_sync(0xffffffffu, rank_sel, j);
            if (selected && rsj < KK && ((ej < e) || (ej == e && rsj < rank_sel))) rank_e++;
        }
        if (selected) srt[wid * KK + rank_e] = e;
        __syncwarp();

        const float yp = y_pred[((size_t)(b * SS + sgl)) * 4 + 0];
        float ql = 0.f, qh = 0.f;
        if (lane < NA) {
            float alpha = c_alphas[lane];
            float pl = 0.5f * alpha * (float)(KK - 1);
            int il = (int)pl; float fl = pl - (float)il;
            ql = srt[wid * KK + il] + fl * (srt[wid * KK + il + 1] - srt[wid * KK + il]);
            float ph = (1.f - 0.5f * alpha) * (float)(KK - 1);
            int ih = (int)ph; float fh = ph - (float)ih;
            qh = srt[wid * KK + ih] + fh * (srt[wid * KK + ih + 1] - srt[wid * KK + ih]);
            size_t oidx = ((size_t)((h * BB + b) * NA + lane)) * SS + sgl;
            out[OFF_QLOW  + oidx] = ql;
            out[OFF_QHIGH + oidx] = qh;
            out[OFF_YLOW  + oidx] = ql + yp;
            out[OFF_YHIGH + oidx] = qh + yp;
        }

        float t = ql + qh;
#pragma unroll
        for (int o = 16; o; o >>= 1) t += __shfl_down_sync(0xffffffffu, t, o);
        if (lane == 0) {
            float me = t * (1.f / 36.f);
            float yt = y[((size_t)(b * SS + sgl)) * 4 + 0];
            float d = yt - (me + yp);
            g_rowsq[(size_t)(b * HH + h) * SS + sgl] = d * d;
        }
        __syncwarp();   // srt reused next row
    }
}

// ---------------- LayerNorm (warp per row) ----------------
__global__ __launch_bounds__(256) void ln_kernel(
    const float* __restrict__ gq, const float* __restrict__ bq,
    const float* __restrict__ gk, const float* __restrict__ bk)
{
    const int warp = threadIdx.x >> 5, lane = threadIdx.x & 31;
    const int row = blockIdx.x * 8 + warp;
    const float* x = g_enc + (size_t)row * DD;
    float v0 = x[lane], v1 = x[lane + 32], v2 = x[lane + 64], v3 = x[lane + 96];
    float s = v0 + v1 + v2 + v3;
#pragma unroll
    for (int o = 16; o; o >>= 1) s += __shfl_xor_sync(0xffffffffu, s, o);
    float mu = s * (1.f / 128.f);
    float d0 = v0 - mu, d1 = v1 - mu, d2 = v2 - mu, d3 = v3 - mu;
    float sq = d0 * d0 + d1 * d1 + d2 * d2 + d3 * d3;
#pragma unroll
    for (int o = 16; o; o >>= 1) sq += __shfl_xor_sync(0xffffffffu, sq, o);
    float rs = rsqrtf(sq * (1.f / 128.f) + 1e-5f);
    const float* g = (row < NTOK) ? gq : gk;
    const float* be = (row < NTOK) ? bq : bk;
    float* o = g_ln + (size_t)row * DD;
    o[lane]      = d0 * rs * g[lane]      + be[lane];
    o[lane + 32] = d1 * rs * g[lane + 32] + be[lane + 32];
    o[lane + 64] = d2 * rs * g[lane + 64] + be[lane + 64];
    o[lane + 96] = d3 * rs * g[lane + 96] + be[lane + 96];
}

// ---------------- passthrough copies ----------------
__global__ void copy_kernel(const float* __restrict__ y,
                            const float* __restrict__ yp,
                            const float* __restrict__ err,
                            float* __restrict__ out)
{
    int i = blockIdx.x * blockDim.x + threadIdx.x;
    if (i < 32768) out[OFF_Y + i] = y[i];
    else if (i < 65536) out[OFF_YPRED + (i - 32768)] = yp[i - 32768];
    else if (i < 73728) { int j = i - 65536; out[OFF_ERR + j] = err[(size_t)j * 4]; }
}

// ---------------- final scalar reduce ----------------
__global__ void reduce_kernel(float* __restrict__ out)
{
    __shared__ float sh[1024];
    float s = 0.f;
    for (int i = threadIdx.x; i < NROW; i += 1024) s += g_rowsq[i];
    sh[threadIdx.x] = s;
    __syncthreads();
    for (int o = 512; o; o >>= 1) {
        if (threadIdx.x < o) sh[threadIdx.x] += sh[threadIdx.x + o];
        __syncthreads();
    }
    if (threadIdx.x == 0) out[OFF_SCORE] = sh[0] * (1.f / (float)NROW);
}

// ---------------- launch ----------------
extern "C" void kernel_launch(void* const* d_in, const int* in_sizes, int n_in,
                              void* d_out, int out_size)
{
    const float* Xt   = (const float*)d_in[0];
    const float* Xs   = (const float*)d_in[1];
    const float* err  = (const float*)d_in[2];
    const float* y    = (const float*)d_in[3];
    const float* ypr  = (const float*)d_in[4];
    const float* W1   = (const float*)d_in[5];
    const float* b1   = (const float*)d_in[6];
    const float* W2   = (const float*)d_in[7];
    const float* b2   = (const float*)d_in[8];
    const float* W3   = (const float*)d_in[9];
    const float* b3   = (const float*)d_in[10];
    const float* W4   = (const float*)d_in[11];
    const float* b4   = (const float*)d_in[12];
    const float* Wq   = (const float*)d_in[13];
    const float* bq   = (const float*)d_in[14];
    const float* Wk   = (const float*)d_in[15];
    const float* bk   = (const float*)d_in[16];
    const float* gq   = (const float*)d_in[17];
    const float* betaq= (const float*)d_in[18];
    const float* gk   = (const float*)d_in[19];
    const float* betak= (const float*)d_in[20];
    float* out = (float*)d_out;

    float *p_h1, *p_h2, *p_enc, *p_ln, *p_qk;
    cudaGetSymbolAddress((void**)&p_h1, g_h1);
    cudaGetSymbolAddress((void**)&p_h2, g_h2);
    cudaGetSymbolAddress((void**)&p_enc, g_enc);
    cudaGetSymbolAddress((void**)&p_ln, g_ln);
    cudaGetSymbolAddress((void**)&p_qk, g_qk);

    cudaFuncSetAttribute(fused_scores_topk,
                         cudaFuncAttributeMaxDynamicSharedMemorySize, SM_FUSED_TOTAL);

    // MLP layer 1 (true rows [0,8192), sim rows [8192,16384))
    sgemm_bias<<<dim3(4, 64), 256>>>(Xt, INF_DIM, W1, HID, b1, p_h1, HID, HID, INF_DIM, 1);
    sgemm_bias<<<dim3(4, 64), 256>>>(Xs, INF_DIM, W1, HID, b1, p_h1 + (size_t)NTOK * HID, HID, HID, INF_DIM, 1);
    // layers 2,3
    sgemm_bias<<<dim3(4, 128), 256>>>(p_h1, HID, W2, HID, b2, p_h2, HID, HID, HID, 1);
    sgemm_bias<<<dim3(4, 128), 256>>>(p_h2, HID, W3, HID, b3, p_h1, HID, HID, HID, 1);
    // layer 4 (no relu) -> enc
    sgemm_bias<<<dim3(1, 128), 256>>>(p_h1, HID, W4, DD, b4, p_enc, DD, DD, HID, 0);
    // layernorm
    ln_kernel<<<NTOK2 / 8, 256>>>(gq, betaq, gk, betak);
    // projections
    sgemm_bias<<<dim3(4, 64), 256>>>(p_ln, DD, Wq, HH * DD, bq, p_qk, HH * DD, HH * DD, DD, 0);
    sgemm_bias<<<dim3(4, 64), 256>>>(p_ln + (size_t)NTOK * DD, DD, Wk, HH * DD, bk,
                                     p_qk + KOFF, HH * DD, HH * DD, DD, 0);
    // bf16 conversion for tensor-core scores
    cvt_bf16_kernel<<<4096, 256>>>(p_qk);
    // fused: scores MMA + top-32 + exact fp32 rescore + quantiles + outputs
    fused_scores_topk<<<dim3(16, 16), 512, SM_FUSED_TOTAL>>>(p_qk, err, y, ypr, out);
    // passthrough copies
    copy_kernel<<<288, 256>>>(y, ypr, err, out);
    // scalar score
    reduce_kernel<<<1, 1024>>>(out);
}

// round 12
// speedup vs baseline: 2.5561x; 2.2532x over previous
#include <cuda_runtime.h>
#include <cuda_bf16.h>
#include <math.h>
#include <stdint.h>

// ---------------- problem constants ----------------
#define BB 4
#define SS 2048
#define INF_DIM 64
#define DD 128
#define HID 400
#define HH 4
#define KK 20
#define NSEL 32
#define NA 18

#define NTOK 8192          // B*S
#define NTOK2 16384        // 2*B*S (true + sim)
#define NROW 32768         // B*H*S
#define KOFF ((size_t)NTOK * (HH * DD))   // offset of k rows inside g_qk

// output offsets (flattened tuple, C-order concat)
#define OFF_SCORE 0
#define OFF_Y     1
#define OFF_YPRED 32769
#define OFF_YLOW  65537
#define OFF_YHIGH 655361
#define OFF_ERR   1245185
#define OFF_QLOW  1253377
#define OFF_QHIGH 1843201
// total 2433025

__constant__ float c_alphas[NA] = {0.05f,0.06f,0.08f,0.1f,0.12f,0.14f,0.15f,0.17f,0.19f,
                                   0.2f,0.21f,0.23f,0.25f,0.3f,0.35f,0.38f,0.4f,0.45f};

// ---------------- scratch (static device allocations) ----------------
__device__ float g_h1[NTOK2 * HID];
__device__ float g_h2[NTOK2 * HID];
__device__ float g_enc[NTOK2 * DD];
__device__ float g_ln[NTOK2 * DD];
__device__ float g_qk[NTOK2 * (HH * DD)];
__device__ __nv_bfloat16 g_qb[(size_t)BB * HH * SS * DD];   // [bh][s][d]
__device__ __nv_bfloat16 g_kb[(size_t)BB * HH * SS * DD];
__device__ float g_rowsq[NROW];

// ---------------- mma.sync helpers (compute_103-safe, sm_80 era PTX) ----------
__device__ __forceinline__ uint32_t smem_u32(const void* p) {
    uint32_t a;
    asm("{ .reg .u64 t; cvta.to.shared.u64 t, %1; cvt.u32.u64 %0, t; }" : "=r"(a) : "l"(p));
    return a;
}
__device__ __forceinline__ void ldsm_x4(uint32_t& r0, uint32_t& r1, uint32_t& r2, uint32_t& r3,
                                        uint32_t addr) {
    asm volatile("ldmatrix.sync.aligned.m8n8.x4.shared.b16 {%0,%1,%2,%3}, [%4];"
                 : "=r"(r0), "=r"(r1), "=r"(r2), "=r"(r3) : "r"(addr));
}
__device__ __forceinline__ void mma_bf16(float* c, const uint32_t* a, const uint32_t* b) {
    asm volatile("mma.sync.aligned.m16n8k16.row.col.f32.bf16.bf16.f32 "
                 "{%0,%1,%2,%3}, {%4,%5,%6,%7}, {%8,%9}, {%0,%1,%2,%3};"
                 : "+f"(c[0]), "+f"(c[1]), "+f"(c[2]), "+f"(c[3])
                 : "r"(a[0]), "r"(a[1]), "r"(a[2]), "r"(a[3]), "r"(b[0]), "r"(b[1]));
}

// swizzled offset within a 128row x 256B tile: row stride 256B, 16 chunks of 16B,
// XOR swizzle applied within each 128B half -> ldmatrix conflict-free.
__device__ __forceinline__ uint32_t tile_swz(int row, int ch) {
    return (uint32_t)row * 256u +
           (uint32_t)(((ch & 8) | ((ch ^ (row & 7)) & 7)) << 4);
}

// ---------------- generic SGEMM: C = act(A @ W + bias) (fp32) -----------------
__global__ __launch_bounds__(256) void sgemm_bias(
    const float* __restrict__ A, int lda,
    const float* __restrict__ W, int ldw,
    const float* __restrict__ bias,
    float* __restrict__ C, int ldc,
    int N, int K, int relu)
{
    __shared__ float As[2][8][128];
    __shared__ float Ws[2][8][128];
    const int tid = threadIdx.x;
    const int row0 = blockIdx.y * 128;
    const int col0 = blockIdx.x * 128;
    const int m0 = (tid >> 4) << 3;
    const int n0 = (tid & 15) << 3;
    const int ar = tid >> 1;
    const int ac = (tid & 1) << 2;
    const int wr = tid >> 5;
    const int wc = (tid & 31) << 2;
    const bool fullN = (col0 + 128 <= N);

    const float* Ap = A + (size_t)(row0 + ar) * lda + ac;

    float acc[8][8];
#pragma unroll
    for (int i = 0; i < 8; i++)
#pragma unroll
        for (int j = 0; j < 8; j++) acc[i][j] = 0.f;

    const int nk = K >> 3;
    float4 av = *reinterpret_cast<const float4*>(Ap);
    float4 wv;
    {
        const float* wp = W + (size_t)wr * ldw + col0 + wc;
        if (fullN) wv = *reinterpret_cast<const float4*>(wp);
        else {
            wv.x = (col0 + wc + 0 < N) ? wp[0] : 0.f;
            wv.y = (col0 + wc + 1 < N) ? wp[1] : 0.f;
            wv.z = (col0 + wc + 2 < N) ? wp[2] : 0.f;
            wv.w = (col0 + wc + 3 < N) ? wp[3] : 0.f;
        }
    }
    As[0][ac + 0][ar] = av.x; As[0][ac + 1][ar] = av.y;
    As[0][ac + 2][ar] = av.z; As[0][ac + 3][ar] = av.w;
    *reinterpret_cast<float4*>(&Ws[0][wr][wc]) = wv;
    __syncthreads();

    int buf = 0;
    for (int t = 0; t < nk; t++) {
        const bool more = (t + 1 < nk);
        if (more) {
            const int k0 = (t + 1) << 3;
            av = *reinterpret_cast<const float4*>(Ap + k0);
            const float* wp = W + (size_t)(k0 + wr) * ldw + col0 + wc;
            if (fullN) wv = *reinterpret_cast<const float4*>(wp);
            else {
                wv.x = (col0 + wc + 0 < N) ? wp[0] : 0.f;
                wv.y = (col0 + wc + 1 < N) ? wp[1] : 0.f;
                wv.z = (col0 + wc + 2 < N) ? wp[2] : 0.f;
                wv.w = (col0 + wc + 3 < N) ? wp[3] : 0.f;
            }
        }
#pragma unroll
        for (int kk = 0; kk < 8; kk++) {
            float4 a0 = *reinterpret_cast<const float4*>(&As[buf][kk][m0]);
            float4 a1 = *reinterpret_cast<const float4*>(&As[buf][kk][m0 + 4]);
            float4 w0 = *reinterpret_cast<const float4*>(&Ws[buf][kk][n0]);
            float4 w1 = *reinterpret_cast<const float4*>(&Ws[buf][kk][n0 + 4]);
            float a[8] = {a0.x, a0.y, a0.z, a0.w, a1.x, a1.y, a1.z, a1.w};
            float w[8] = {w0.x, w0.y, w0.z, w0.w, w1.x, w1.y, w1.z, w1.w};
#pragma unroll
            for (int i = 0; i < 8; i++)
#pragma unroll
                for (int j = 0; j < 8; j++) acc[i][j] = fmaf(a[i], w[j], acc[i][j]);
        }
        if (more) {
            const int nb = buf ^ 1;
            As[nb][ac + 0][ar] = av.x; As[nb][ac + 1][ar] = av.y;
            As[nb][ac + 2][ar] = av.z; As[nb][ac + 3][ar] = av.w;
            *reinterpret_cast<float4*>(&Ws[nb][wr][wc]) = wv;
            __syncthreads();
            buf = nb;
        }
    }

#pragma unroll
    for (int j = 0; j < 8; j++) {
        int c = col0 + n0 + j;
        if (c < N) {
            float bb = bias[c];
#pragma unroll
            for (int i = 0; i < 8; i++) {
                float v = acc[i][j] + bb;
                if (relu) v = fmaxf(v, 0.f);
                C[(size_t)(row0 + m0 + i) * ldc + c] = v;
            }
        }
    }
}

// ---------------- fp32 -> bf16 conversion, [b,s,h,d] -> [bh][s][d] ------------
__global__ __launch_bounds__(256) void cvt_bf16_kernel(const float* __restrict__ qk)
{
    int idx = blockIdx.x * 256 + threadIdx.x;     // < 1048576 (float4 groups)
    int d4 = idx & 31;
    int s  = (idx >> 5) & 2047;
    int bh = idx >> 16;
    int b = bh >> 2, h = bh & 3;
    size_t src = ((size_t)(b * SS + s)) * (HH * DD) + h * DD + d4 * 4;
    float4 q = *reinterpret_cast<const float4*>(qk + src);
    float4 k = *reinterpret_cast<const float4*>(qk + KOFF + src);
    __nv_bfloat162 q01 = __floats2bfloat162_rn(q.x, q.y);
    __nv_bfloat162 q23 = __floats2bfloat162_rn(q.z, q.w);
    __nv_bfloat162 k01 = __floats2bfloat162_rn(k.x, k.y);
    __nv_bfloat162 k23 = __floats2bfloat162_rn(k.z, k.w);
    uint2* qd = reinterpret_cast<uint2*>(g_qb) + idx;
    uint2* kd = reinterpret_cast<uint2*>(g_kb) + idx;
    *qd = make_uint2(*(uint32_t*)&q01, *(uint32_t*)&q23);
    *kd = make_uint2(*(uint32_t*)&k01, *(uint32_t*)&k23);
}

// ---------------- fused scores MMA + top-32 + exact rescore + quantiles -------
// grid (16 row-tiles, 16 bh), 512 threads (16 warps, 32x32 warp tiles).
// Top-32 list lives in registers distributed across each warp:
// lane l holds the rank-l (value, index) pair for each of the warp's 8 rows.
// smem layout (dynamic):
#define SM_QT   0          // Q bf16 tile, 32768 B (swizzled, 256B row stride)
#define SM_KT   32768      // K bf16 tile, 32768 B
#define SM_SC   65536      // scores f32 [128][132] = 67584 B
#define SM_QF   133120     // per-warp q fp32 row [16][128] = 8192 B
#define SM_SRT  141312     // per-warp sorted errs [16][20] = 1280 B
#define SM_FUSED_TOTAL 142592

__global__ __launch_bounds__(512, 1) void fused_scores_topk(
    const float* __restrict__ qk,
    const float* __restrict__ errors,
    const float* __restrict__ y,
    const float* __restrict__ y_pred,
    float* __restrict__ out)
{
    extern __shared__ char smem[];
    const uint32_t sb = smem_u32(smem);
    float* sc  = reinterpret_cast<float*>(smem + SM_SC);
    float* qf  = reinterpret_cast<float*>(smem + SM_QF);
    float* srt = reinterpret_cast<float*>(smem + SM_SRT);

    const int tid = threadIdx.x;
    const int wid = tid >> 5, lane = tid & 31;
    const int rt0 = blockIdx.x * 128;     // q row tile base
    const int bh = blockIdx.y;
    const int b = bh >> 2, h = bh & 3;
    const float ninf = __int_as_float(0xff800000);
    const unsigned FULL = 0xffffffffu;

    // distributed-register top-32 lists: lane l = rank l, per row rr
    float tv[8];
    int   ti[8];
#pragma unroll
    for (int rr = 0; rr < 8; rr++) { tv[rr] = ninf; ti[rr] = 0; }

    // load Q tile (swizzled)
    const __nv_bfloat16* qsrc = g_qb + ((size_t)bh * SS + rt0) * DD;
#pragma unroll
    for (int i = 0; i < 4; i++) {
        int idx = tid + i * 512;          // 0..2047
        int row = idx >> 4, ch = idx & 15;
        *reinterpret_cast<uint4*>(smem + SM_QT + tile_swz(row, ch)) =
            *reinterpret_cast<const uint4*>(qsrc + (size_t)row * DD + ch * 8);
    }

    const int wm0 = (wid & 3) * 32;       // 4 m-warps
    const int wn0 = (wid >> 2) * 32;      // 4 n-warps

    // A fragment bases
    uint32_t abase[2]; int ax[2];
#pragma unroll
    for (int mf = 0; mf < 2; mf++) {
        int r = wm0 + mf * 16 + (lane & 15);
        abase[mf] = sb + SM_QT + (uint32_t)r * 256u;
        ax[mf] = r & 7;
    }
    const int alb = lane >> 4;
    // B fragment bases
    uint32_t bbase[2]; int bx[2];
#pragma unroll
    for (int nf2 = 0; nf2 < 2; nf2++) {
        int r = wn0 + nf2 * 16 + (lane & 7) + ((lane & 16) >> 1);
        bbase[nf2] = sb + SM_KT + (uint32_t)r * 256u;
        bx[nf2] = r & 7;
    }
    const int blb = (lane >> 3) & 1;

    const float scale = 0.08838834764831845f;   // 1/sqrt(128)

    for (int ct = 0; ct < 16; ct++) {
        __syncthreads();   // sc/Kt consumed by previous iteration
        // load K tile (rows ct*128..+127)
        const __nv_bfloat16* ksrc = g_kb + ((size_t)bh * SS + ct * 128) * DD;
#pragma unroll
        for (int i = 0; i < 4; i++) {
            int idx = tid + i * 512;
            int row = idx >> 4, ch = idx & 15;
            *reinterpret_cast<uint4*>(smem + SM_KT + tile_swz(row, ch)) =
                *reinterpret_cast<const uint4*>(ksrc + (size_t)row * DD + ch * 8);
        }
        __syncthreads();

        float acc[2][4][4];
#pragma unroll
        for (int mf = 0; mf < 2; mf++)
#pragma unroll
            for (int nf = 0; nf < 4; nf++)
#pragma unroll
                for (int i = 0; i < 4; i++) acc[mf][nf][i] = 0.f;

#pragma unroll
        for (int s = 0; s < 8; s++) {
            uint32_t a[2][4], bfr[4][2];
            const int ca = 2 * s + alb;
            const int cb = 2 * s + blb;
#pragma unroll
            for (int mf = 0; mf < 2; mf++)
                ldsm_x4(a[mf][0], a[mf][1], a[mf][2], a[mf][3],
                        abase[mf] + (uint32_t)(((ca & 8) | ((ca ^ ax[mf]) & 7)) << 4));
#pragma unroll
            for (int nf2 = 0; nf2 < 2; nf2++) {
                uint32_t r0, r1, r2, r3;
                ldsm_x4(r0, r1, r2, r3,
                        bbase[nf2] + (uint32_t)(((cb & 8) | ((cb ^ bx[nf2]) & 7)) << 4));
                bfr[nf2 * 2][0] = r0; bfr[nf2 * 2][1] = r1;
                bfr[nf2 * 2 + 1][0] = r2; bfr[nf2 * 2 + 1][1] = r3;
            }
#pragma unroll
            for (int mf = 0; mf < 2; mf++)
#pragma unroll
                for (int nf = 0; nf < 4; nf++)
                    mma_bf16(acc[mf][nf], a[mf], bfr[nf]);
        }

        // epilogue: scaled scores (diag-masked) -> smem sc
        const int qr = lane >> 2, qc = (lane & 3) * 2;
#pragma unroll
        for (int mf = 0; mf < 2; mf++) {
            int r1 = wm0 + mf * 16 + qr;
            int r2 = r1 + 8;
            int gr1 = rt0 + r1, gr2 = rt0 + r2;
#pragma unroll
            for (int nf = 0; nf < 4; nf++) {
                int cl = wn0 + nf * 8 + qc;
                int gc = ct * 128 + cl;
                float2 v1, v2;
                v1.x = (gr1 == gc)     ? ninf : acc[mf][nf][0] * scale;
                v1.y = (gr1 == gc + 1) ? ninf : acc[mf][nf][1] * scale;
                v2.x = (gr2 == gc)     ? ninf : acc[mf][nf][2] * scale;
                v2.y = (gr2 == gc + 1) ? ninf : acc[mf][nf][3] * scale;
                *reinterpret_cast<float2*>(&sc[r1 * 132 + cl]) = v1;
                *reinterpret_cast<float2*>(&sc[r2 * 132 + cl]) = v2;
            }
        }
        __syncthreads();

        // top-32 streaming update, warp-parallel register insertion.
        // warp handles rows wid*8 .. wid*8+7
#pragma unroll
        for (int rr = 0; rr < 8; rr++) {
            const int r = wid * 8 + rr;
            float thr = __shfl_sync(FULL, tv[rr], 31);
#pragma unroll
            for (int j = 0; j < 4; j++) {
                float x = sc[r * 132 + lane + 32 * j];
                unsigned m = __ballot_sync(FULL, x > thr);
                while (m) {
                    int ld = __ffs(m) - 1; m &= m - 1;
                    float bv = __shfl_sync(FULL, x, ld);
                    if (bv > thr) {
                        int bc = ct * 128 + 32 * j + ld;
                        unsigned gt = __ballot_sync(FULL, tv[rr] > bv);
                        int pos = __popc(gt);
                        float pv = __shfl_up_sync(FULL, tv[rr], 1);
                        int   pi = __shfl_up_sync(FULL, ti[rr], 1);
                        if (lane == pos)      { tv[rr] = bv; ti[rr] = bc; }
                        else if (lane > pos)  { tv[rr] = pv; ti[rr] = pi; }
                        thr = __shfl_sync(FULL, tv[rr], 31);
                    }
                }
            }
        }
    }
    __syncthreads();

    // ---- exact fp32 rescore + quantiles: warp per row, 8 rows ----
#pragma unroll
    for (int rr = 0; rr < 8; rr++) {
        const int r = wid * 8 + rr;
        const int sgl = rt0 + r;                        // s index in [0,2048)
        // stage q fp32 row for broadcast
        const float* qrow = qk + ((size_t)(b * SS + sgl)) * (HH * DD) + h * DD;
        *reinterpret_cast<float4*>(&qf[wid * 128 + lane * 4]) =
            *reinterpret_cast<const float4*>(qrow + lane * 4);
        __syncwarp();

        const int my_m = ti[rr];
        const float* krow = qk + KOFF + ((size_t)(b * SS + my_m)) * (HH * DD) + h * DD;
        float ex = 0.f;
#pragma unroll
        for (int d4 = 0; d4 < 32; d4++) {
            float4 kv = *reinterpret_cast<const float4*>(krow + d4 * 4);
            float4 qv = *reinterpret_cast<const float4*>(&qf[wid * 128 + d4 * 4]);
            ex = fmaf(qv.x, kv.x, ex);
            ex = fmaf(qv.y, kv.y, ex);
            ex = fmaf(qv.z, kv.z, ex);
            ex = fmaf(qv.w, kv.w, ex);
        }

        // rank among 32 by (exact score desc, index asc)
        int rank_sel = 0;
#pragma unroll
        for (int j = 0; j < NSEL; j++) {
            float sj = __shfl_sync(FULL, ex, j);
            int   mj = __shfl_sync(FULL, my_m, j);
            if ((sj > ex) || (sj == ex && mj < my_m)) rank_sel++;
        }
        const bool selected = (rank_sel < KK);

        float e = selected ? errors[((size_t)(b * SS + my_m)) * 4 + 0] : 0.f;

        // sort the 20 selected error values (ascending)
        int rank_e = 0;
#pragma unroll
        for (int j = 0; j < NSEL; j++) {
            float ej  = __shfl_sync(FULL, e, j);
            int   rsj = __shfl_sync(FULL, rank_sel, j);
            if (selected && rsj < KK && ((ej < e) || (ej == e && rsj < rank_sel))) rank_e++;
        }
        if (selected) srt[wid * KK + rank_e] = e;
        __syncwarp();

        const float yp = y_pred[((size_t)(b * SS + sgl)) * 4 + 0];
        float ql = 0.f, qh = 0.f;
        if (lane < NA) {
            float alpha = c_alphas[lane];
            float pl = 0.5f * alpha * (float)(KK - 1);
            int il = (int)pl; float fl = pl - (float)il;
            ql = srt[wid * KK + il] + fl * (srt[wid * KK + il + 1] - srt[wid * KK + il]);
            float ph = (1.f - 0.5f * alpha) * (float)(KK - 1);
            int ih = (int)ph; float fh = ph - (float)ih;
            qh = srt[wid * KK + ih] + fh * (srt[wid * KK + ih + 1] - srt[wid * KK + ih]);
            size_t oidx = ((size_t)((h * BB + b) * NA + lane)) * SS + sgl;
            out[OFF_QLOW  + oidx] = ql;
            out[OFF_QHIGH + oidx] = qh;
            out[OFF_YLOW  + oidx] = ql + yp;
            out[OFF_YHIGH + oidx] = qh + yp;
        }

        float t = ql + qh;
#pragma unroll
        for (int o = 16; o; o >>= 1) t += __shfl_down_sync(FULL, t, o);
        if (lane == 0) {
            float me = t * (1.f / 36.f);
            float yt = y[((size_t)(b * SS + sgl)) * 4 + 0];
            float d = yt - (me + yp);
            g_rowsq[(size_t)(b * HH + h) * SS + sgl] = d * d;
        }
        __syncwarp();   // srt reused next row
    }
}

// ---------------- LayerNorm (warp per row) ----------------
__global__ __launch_bounds__(256) void ln_kernel(
    const float* __restrict__ gq, const float* __restrict__ bq,
    const float* __restrict__ gk, const float* __restrict__ bk)
{
    const int warp = threadIdx.x >> 5, lane = threadIdx.x & 31;
    const int row = blockIdx.x * 8 + warp;
    const float* x = g_enc + (size_t)row * DD;
    float v0 = x[lane], v1 = x[lane + 32], v2 = x[lane + 64], v3 = x[lane + 96];
    float s = v0 + v1 + v2 + v3;
#pragma unroll
    for (int o = 16; o; o >>= 1) s += __shfl_xor_sync(0xffffffffu, s, o);
    float mu = s * (1.f / 128.f);
    float d0 = v0 - mu, d1 = v1 - mu, d2 = v2 - mu, d3 = v3 - mu;
    float sq = d0 * d0 + d1 * d1 + d2 * d2 + d3 * d3;
#pragma unroll
    for (int o = 16; o; o >>= 1) sq += __shfl_xor_sync(0xffffffffu, sq, o);
    float rs = rsqrtf(sq * (1.f / 128.f) + 1e-5f);
    const float* g = (row < NTOK) ? gq : gk;
    const float* be = (row < NTOK) ? bq : bk;
    float* o = g_ln + (size_t)row * DD;
    o[lane]      = d0 * rs * g[lane]      + be[lane];
    o[lane + 32] = d1 * rs * g[lane + 32] + be[lane + 32];
    o[lane + 64] = d2 * rs * g[lane + 64] + be[lane + 64];
    o[lane + 96] = d3 * rs * g[lane + 96] + be[lane + 96];
}

// ---------------- passthrough copies ----------------
__global__ void copy_kernel(const float* __restrict__ y,
                            const float* __restrict__ yp,
                            const float* __restrict__ err,
                            float* __restrict__ out)
{
    int i = blockIdx.x * blockDim.x + threadIdx.x;
    if (i < 32768) out[OFF_Y + i] = y[i];
    else if (i < 65536) out[OFF_YPRED + (i - 32768)] = yp[i - 32768];
    else if (i < 73728) { int j = i - 65536; out[OFF_ERR + j] = err[(size_t)j * 4]; }
}

// ---------------- final scalar reduce ----------------
__global__ void reduce_kernel(float* __restrict__ out)
{
    __shared__ float sh[1024];
    float s = 0.f;
    for (int i = threadIdx.x; i < NROW; i += 1024) s += g_rowsq[i];
    sh[threadIdx.x] = s;
    __syncthreads();
    for (int o = 512; o; o >>= 1) {
        if (threadIdx.x < o) sh[threadIdx.x] += sh[threadIdx.x + o];
        __syncthreads();
    }
    if (threadIdx.x == 0) out[OFF_SCORE] = sh[0] * (1.f / (float)NROW);
}

// ---------------- launch ----------------
extern "C" void kernel_launch(void* const* d_in, const int* in_sizes, int n_in,
                              void* d_out, int out_size)
{
    const float* Xt   = (const float*)d_in[0];
    const float* Xs   = (const float*)d_in[1];
    const float* err  = (const float*)d_in[2];
    const float* y    = (const float*)d_in[3];
    const float* ypr  = (const float*)d_in[4];
    const float* W1   = (const float*)d_in[5];
    const float* b1   = (const float*)d_in[6];
    const float* W2   = (const float*)d_in[7];
    const float* b2   = (const float*)d_in[8];
    const float* W3   = (const float*)d_in[9];
    const float* b3   = (const float*)d_in[10];
    const float* W4   = (const float*)d_in[11];
    const float* b4   = (const float*)d_in[12];
    const float* Wq   = (const float*)d_in[13];
    const float* bq   = (const float*)d_in[14];
    const float* Wk   = (const float*)d_in[15];
    const float* bk   = (const float*)d_in[16];
    const float* gq   = (const float*)d_in[17];
    const float* betaq= (const float*)d_in[18];
    const float* gk   = (const float*)d_in[19];
    const float* betak= (const float*)d_in[20];
    float* out = (float*)d_out;

    float *p_h1, *p_h2, *p_enc, *p_ln, *p_qk;
    cudaGetSymbolAddress((void**)&p_h1, g_h1);
    cudaGetSymbolAddress((void**)&p_h2, g_h2);
    cudaGetSymbolAddress((void**)&p_enc, g_enc);
    cudaGetSymbolAddress((void**)&p_ln, g_ln);
    cudaGetSymbolAddress((void**)&p_qk, g_qk);

    cudaFuncSetAttribute(fused_scores_topk,
                         cudaFuncAttributeMaxDynamicSharedMemorySize, SM_FUSED_TOTAL);

    // MLP layer 1 (true rows [0,8192), sim rows [8192,16384))
    sgemm_bias<<<dim3(4, 64), 256>>>(Xt, INF_DIM, W1, HID, b1, p_h1, HID, HID, INF_DIM, 1);
    sgemm_bias<<<dim3(4, 64), 256>>>(Xs, INF_DIM, W1, HID, b1, p_h1 + (size_t)NTOK * HID, HID, HID, INF_DIM, 1);
    // layers 2,3
    sgemm_bias<<<dim3(4, 128), 256>>>(p_h1, HID, W2, HID, b2, p_h2, HID, HID, HID, 1);
    sgemm_bias<<<dim3(4, 128), 256>>>(p_h2, HID, W3, HID, b3, p_h1, HID, HID, HID, 1);
    // layer 4 (no relu) -> enc
    sgemm_bias<<<dim3(1, 128), 256>>>(p_h1, HID, W4, DD, b4, p_enc, DD, DD, HID, 0);
    // layernorm
    ln_kernel<<<NTOK2 / 8, 256>>>(gq, betaq, gk, betak);
    // projections
    sgemm_bias<<<dim3(4, 64), 256>>>(p_ln, DD, Wq, HH * DD, bq, p_qk, HH * DD, HH * DD, DD, 0);
    sgemm_bias<<<dim3(4, 64), 256>>>(p_ln + (size_t)NTOK * DD, DD, Wk, HH * DD, bk,
                                     p_qk + KOFF, HH * DD, HH * DD, DD, 0);
    // bf16 conversion for tensor-core scores
    cvt_bf16_kernel<<<4096, 256>>>(p_qk);
    // fused: scores MMA + register top-32 + exact fp32 rescore + quantiles
    fused_scores_topk<<<dim3(16, 16), 512, SM_FUSED_TOTAL>>>(p_qk, err, y, ypr, out);
    // passthrough copies
    copy_kernel<<<288, 256>>>(y, ypr, err, out);
    // scalar score
    reduce_kernel<<<1, 1024>>>(out);
}

// round 13
// speedup vs baseline: 2.5908x; 1.0136x over previous
#include <cuda_runtime.h>
#include <cuda_bf16.h>
#include <math.h>
#include <stdint.h>

// ---------------- problem constants ----------------
#define BB 4
#define SS 2048
#define INF_DIM 64
#define DD 128
#define HID 400
#define HH 4
#define KK 20
#define NSEL 32
#define NA 18

#define NTOK 8192          // B*S
#define NTOK2 16384        // 2*B*S (true + sim)
#define NROW 32768         // B*H*S
#define KOFF ((size_t)NTOK * (HH * DD))   // offset of k rows inside g_qk

// output offsets (flattened tuple, C-order concat)
#define OFF_SCORE 0
#define OFF_Y     1
#define OFF_YPRED 32769
#define OFF_YLOW  65537
#define OFF_YHIGH 655361
#define OFF_ERR   1245185
#define OFF_QLOW  1253377
#define OFF_QHIGH 1843201
// total 2433025

__constant__ float c_alphas[NA] = {0.05f,0.06f,0.08f,0.1f,0.12f,0.14f,0.15f,0.17f,0.19f,
                                   0.2f,0.21f,0.23f,0.25f,0.3f,0.35f,0.38f,0.4f,0.45f};

// ---------------- scratch (static device allocations) ----------------
__device__ float g_h1[NTOK2 * HID];
__device__ float g_h2[NTOK2 * HID];
__device__ float g_enc[NTOK2 * DD];
__device__ float g_ln[NTOK2 * DD];
__device__ float g_qk[NTOK2 * (HH * DD)];
__device__ __nv_bfloat16 g_qb[(size_t)BB * HH * SS * DD];   // [bh][s][d]
__device__ __nv_bfloat16 g_kb[(size_t)BB * HH * SS * DD];
__device__ float g_rowsq[NROW];

// ---------------- mma.sync helpers (compute_103-safe, sm_80 era PTX) ----------
__device__ __forceinline__ uint32_t smem_u32(const void* p) {
    uint32_t a;
    asm("{ .reg .u64 t; cvta.to.shared.u64 t, %1; cvt.u32.u64 %0, t; }" : "=r"(a) : "l"(p));
    return a;
}
__device__ __forceinline__ void ldsm_x4(uint32_t& r0, uint32_t& r1, uint32_t& r2, uint32_t& r3,
                                        uint32_t addr) {
    asm volatile("ldmatrix.sync.aligned.m8n8.x4.shared.b16 {%0,%1,%2,%3}, [%4];"
                 : "=r"(r0), "=r"(r1), "=r"(r2), "=r"(r3) : "r"(addr));
}
__device__ __forceinline__ void mma_bf16(float* c, const uint32_t* a, const uint32_t* b) {
    asm volatile("mma.sync.aligned.m16n8k16.row.col.f32.bf16.bf16.f32 "
                 "{%0,%1,%2,%3}, {%4,%5,%6,%7}, {%8,%9}, {%0,%1,%2,%3};"
                 : "+f"(c[0]), "+f"(c[1]), "+f"(c[2]), "+f"(c[3])
                 : "r"(a[0]), "r"(a[1]), "r"(a[2]), "r"(a[3]), "r"(b[0]), "r"(b[1]));
}

// swizzled offset within a tile: row stride 256B, 16 chunks of 16B,
// XOR swizzle applied within each 128B half -> ldmatrix conflict-free.
__device__ __forceinline__ uint32_t tile_swz(int row, int ch) {
    return (uint32_t)row * 256u +
           (uint32_t)(((ch & 8) | ((ch ^ (row & 7)) & 7)) << 4);
}

// ---------------- generic SGEMM: C = act(A @ W + bias) (fp32) -----------------
__global__ __launch_bounds__(256) void sgemm_bias(
    const float* __restrict__ A, int lda,
    const float* __restrict__ W, int ldw,
    const float* __restrict__ bias,
    float* __restrict__ C, int ldc,
    int N, int K, int relu)
{
    __shared__ float As[2][8][128];
    __shared__ float Ws[2][8][128];
    const int tid = threadIdx.x;
    const int row0 = blockIdx.y * 128;
    const int col0 = blockIdx.x * 128;
    const int m0 = (tid >> 4) << 3;
    const int n0 = (tid & 15) << 3;
    const int ar = tid >> 1;
    const int ac = (tid & 1) << 2;
    const int wr = tid >> 5;
    const int wc = (tid & 31) << 2;
    const bool fullN = (col0 + 128 <= N);

    const float* Ap = A + (size_t)(row0 + ar) * lda + ac;

    float acc[8][8];
#pragma unroll
    for (int i = 0; i < 8; i++)
#pragma unroll
        for (int j = 0; j < 8; j++) acc[i][j] = 0.f;

    const int nk = K >> 3;
    float4 av = *reinterpret_cast<const float4*>(Ap);
    float4 wv;
    {
        const float* wp = W + (size_t)wr * ldw + col0 + wc;
        if (fullN) wv = *reinterpret_cast<const float4*>(wp);
        else {
            wv.x = (col0 + wc + 0 < N) ? wp[0] : 0.f;
            wv.y = (col0 + wc + 1 < N) ? wp[1] : 0.f;
            wv.z = (col0 + wc + 2 < N) ? wp[2] : 0.f;
            wv.w = (col0 + wc + 3 < N) ? wp[3] : 0.f;
        }
    }
    As[0][ac + 0][ar] = av.x; As[0][ac + 1][ar] = av.y;
    As[0][ac + 2][ar] = av.z; As[0][ac + 3][ar] = av.w;
    *reinterpret_cast<float4*>(&Ws[0][wr][wc]) = wv;
    __syncthreads();

    int buf = 0;
    for (int t = 0; t < nk; t++) {
        const bool more = (t + 1 < nk);
        if (more) {
            const int k0 = (t + 1) << 3;
            av = *reinterpret_cast<const float4*>(Ap + k0);
            const float* wp = W + (size_t)(k0 + wr) * ldw + col0 + wc;
            if (fullN) wv = *reinterpret_cast<const float4*>(wp);
            else {
                wv.x = (col0 + wc + 0 < N) ? wp[0] : 0.f;
                wv.y = (col0 + wc + 1 < N) ? wp[1] : 0.f;
                wv.z = (col0 + wc + 2 < N) ? wp[2] : 0.f;
                wv.w = (col0 + wc + 3 < N) ? wp[3] : 0.f;
            }
        }
#pragma unroll
        for (int kk = 0; kk < 8; kk++) {
            float4 a0 = *reinterpret_cast<const float4*>(&As[buf][kk][m0]);
            float4 a1 = *reinterpret_cast<const float4*>(&As[buf][kk][m0 + 4]);
            float4 w0 = *reinterpret_cast<const float4*>(&Ws[buf][kk][n0]);
            float4 w1 = *reinterpret_cast<const float4*>(&Ws[buf][kk][n0 + 4]);
            float a[8] = {a0.x, a0.y, a0.z, a0.w, a1.x, a1.y, a1.z, a1.w};
            float w[8] = {w0.x, w0.y, w0.z, w0.w, w1.x, w1.y, w1.z, w1.w};
#pragma unroll
            for (int i = 0; i < 8; i++)
#pragma unroll
                for (int j = 0; j < 8; j++) acc[i][j] = fmaf(a[i], w[j], acc[i][j]);
        }
        if (more) {
            const int nb = buf ^ 1;
            As[nb][ac + 0][ar] = av.x; As[nb][ac + 1][ar] = av.y;
            As[nb][ac + 2][ar] = av.z; As[nb][ac + 3][ar] = av.w;
            *reinterpret_cast<float4*>(&Ws[nb][wr][wc]) = wv;
            __syncthreads();
            buf = nb;
        }
    }

#pragma unroll
    for (int j = 0; j < 8; j++) {
        int c = col0 + n0 + j;
        if (c < N) {
            float bb = bias[c];
#pragma unroll
            for (int i = 0; i < 8; i++) {
                float v = acc[i][j] + bb;
                if (relu) v = fmaxf(v, 0.f);
                C[(size_t)(row0 + m0 + i) * ldc + c] = v;
            }
        }
    }
}

// ---------------- fp32 -> bf16 conversion, [b,s,h,d] -> [bh][s][d] ------------
__global__ __launch_bounds__(256) void cvt_bf16_kernel(const float* __restrict__ qk)
{
    int idx = blockIdx.x * 256 + threadIdx.x;     // < 1048576 (float4 groups)
    int d4 = idx & 31;
    int s  = (idx >> 5) & 2047;
    int bh = idx >> 16;
    int b = bh >> 2, h = bh & 3;
    size_t src = ((size_t)(b * SS + s)) * (HH * DD) + h * DD + d4 * 4;
    float4 q = *reinterpret_cast<const float4*>(qk + src);
    float4 k = *reinterpret_cast<const float4*>(qk + KOFF + src);
    __nv_bfloat162 q01 = __floats2bfloat162_rn(q.x, q.y);
    __nv_bfloat162 q23 = __floats2bfloat162_rn(q.z, q.w);
    __nv_bfloat162 k01 = __floats2bfloat162_rn(k.x, k.y);
    __nv_bfloat162 k23 = __floats2bfloat162_rn(k.z, k.w);
    uint2* qd = reinterpret_cast<uint2*>(g_qb) + idx;
    uint2* kd = reinterpret_cast<uint2*>(g_kb) + idx;
    *qd = make_uint2(*(uint32_t*)&q01, *(uint32_t*)&q23);
    *kd = make_uint2(*(uint32_t*)&k01, *(uint32_t*)&k23);
}

// ---------------- fused scores MMA + top-32 + exact rescore + quantiles -------
// grid (32 row-tiles of 64, 16 bh), 256 threads (8 warps, warp tile 16x64).
// 2 CTAs/SM (smem 87.7KB) -> phases of co-resident CTAs overlap.
// Top-32 list in registers distributed across each warp (lane l = rank l).
// smem layout (dynamic):
#define SM_QT   0          // Q bf16 tile 64x128, 16384 B (swizzled, 256B row stride)
#define SM_KT   16384      // K bf16 tile 128x128, 32768 B
#define SM_SC   49152      // scores f32 [64][132] = 33792 B
#define SM_QF   82944      // per-warp q fp32 row [8][128] = 4096 B
#define SM_SRT  87040      // per-warp sorted errs [8][20] = 640 B
#define SM_FUSED_TOTAL 87680

__global__ __launch_bounds__(256, 2) void fused_scores_topk(
    const float* __restrict__ qk,
    const float* __restrict__ errors,
    const float* __restrict__ y,
    const float* __restrict__ y_pred,
    float* __restrict__ out)
{
    extern __shared__ char smem[];
    const uint32_t sb = smem_u32(smem);
    float* sc  = reinterpret_cast<float*>(smem + SM_SC);
    float* qf  = reinterpret_cast<float*>(smem + SM_QF);
    float* srt = reinterpret_cast<float*>(smem + SM_SRT);

    const int tid = threadIdx.x;
    const int wid = tid >> 5, lane = tid & 31;
    const int rt0 = blockIdx.x * 64;      // q row tile base
    const int bh = blockIdx.y;
    const int b = bh >> 2, h = bh & 3;
    const float ninf = __int_as_float(0xff800000);
    const unsigned FULL = 0xffffffffu;

    // distributed-register top-32 lists: lane l = rank l, per row rr (8 rows/warp)
    float tv[8];
    int   ti[8];
#pragma unroll
    for (int rr = 0; rr < 8; rr++) { tv[rr] = ninf; ti[rr] = 0; }

    // load Q tile 64x128 (swizzled): 1024 chunks
    const __nv_bfloat16* qsrc = g_qb + ((size_t)bh * SS + rt0) * DD;
#pragma unroll
    for (int i = 0; i < 4; i++) {
        int idx = tid + i * 256;          // 0..1023
        int row = idx >> 4, ch = idx & 15;
        *reinterpret_cast<uint4*>(smem + SM_QT + tile_swz(row, ch)) =
            *reinterpret_cast<const uint4*>(qsrc + (size_t)row * DD + ch * 8);
    }

    const int wm0 = (wid & 3) * 16;       // 4 m-warps (16 rows each)
    const int wn0 = (wid >> 2) * 64;      // 2 n-warps (64 cols each)

    // A fragment base (single m-fragment of 16 rows)
    uint32_t abase; int ax;
    {
        int r = wm0 + (lane & 15);
        abase = sb + SM_QT + (uint32_t)r * 256u;
        ax = r & 7;
    }
    const int alb = lane >> 4;
    // B fragment bases: 4 x (16-col pair fragments)
    uint32_t bbase[4]; int bx[4];
#pragma unroll
    for (int nf2 = 0; nf2 < 4; nf2++) {
        int r = wn0 + nf2 * 16 + (lane & 7) + ((lane & 16) >> 1);
        bbase[nf2] = sb + SM_KT + (uint32_t)r * 256u;
        bx[nf2] = r & 7;
    }
    const int blb = (lane >> 3) & 1;

    const float scale = 0.08838834764831845f;   // 1/sqrt(128)

    for (int ct = 0; ct < 16; ct++) {
        __syncthreads();   // sc/Kt consumed by previous iteration
        // load K tile 128x128 (rows ct*128..+127): 2048 chunks
        const __nv_bfloat16* ksrc = g_kb + ((size_t)bh * SS + ct * 128) * DD;
#pragma unroll
        for (int i = 0; i < 8; i++) {
            int idx = tid + i * 256;
            int row = idx >> 4, ch = idx & 15;
            *reinterpret_cast<uint4*>(smem + SM_KT + tile_swz(row, ch)) =
                *reinterpret_cast<const uint4*>(ksrc + (size_t)row * DD + ch * 8);
        }
        __syncthreads();

        float acc[8][4];
#pragma unroll
        for (int nf = 0; nf < 8; nf++)
#pragma unroll
            for (int i = 0; i < 4; i++) acc[nf][i] = 0.f;

#pragma unroll
        for (int s = 0; s < 8; s++) {
            uint32_t a[4], bfr[8][2];
            const int ca = 2 * s + alb;
            const int cb = 2 * s + blb;
            ldsm_x4(a[0], a[1], a[2], a[3],
                    abase + (uint32_t)(((ca & 8) | ((ca ^ ax) & 7)) << 4));
#pragma unroll
            for (int nf2 = 0; nf2 < 4; nf2++) {
                uint32_t r0, r1, r2, r3;
                ldsm_x4(r0, r1, r2, r3,
                        bbase[nf2] + (uint32_t)(((cb & 8) | ((cb ^ bx[nf2]) & 7)) << 4));
                bfr[nf2 * 2][0] = r0; bfr[nf2 * 2][1] = r1;
                bfr[nf2 * 2 + 1][0] = r2; bfr[nf2 * 2 + 1][1] = r3;
            }
#pragma unroll
            for (int nf = 0; nf < 8; nf++)
                mma_bf16(acc[nf], a, bfr[nf]);
        }

        // epilogue: scaled scores (diag-masked) -> smem sc
        const int qr = lane >> 2, qc = (lane & 3) * 2;
        {
            int r1 = wm0 + qr;
            int r2 = r1 + 8;
            int gr1 = rt0 + r1, gr2 = rt0 + r2;
#pragma unroll
            for (int nf = 0; nf < 8; nf++) {
                int cl = wn0 + nf * 8 + qc;
                int gc = ct * 128 + cl;
                float2 v1, v2;
                v1.x = (gr1 == gc)     ? ninf : acc[nf][0] * scale;
                v1.y = (gr1 == gc + 1) ? ninf : acc[nf][1] * scale;
                v2.x = (gr2 == gc)     ? ninf : acc[nf][2] * scale;
                v2.y = (gr2 == gc + 1) ? ninf : acc[nf][3] * scale;
                *reinterpret_cast<float2*>(&sc[r1 * 132 + cl]) = v1;
                *reinterpret_cast<float2*>(&sc[r2 * 132 + cl]) = v2;
            }
        }
        __syncthreads();

        // top-32 streaming update, warp-parallel register insertion.
        // warp handles rows wid*8 .. wid*8+7
#pragma unroll
        for (int rr = 0; rr < 8; rr++) {
            const int r = wid * 8 + rr;
            float thr = __shfl_sync(FULL, tv[rr], 31);
#pragma unroll
            for (int j = 0; j < 4; j++) {
                float x = sc[r * 132 + lane + 32 * j];
                unsigned m = __ballot_sync(FULL, x > thr);
                while (m) {
                    int ld = __ffs(m) - 1; m &= m - 1;
                    float bv = __shfl_sync(FULL, x, ld);
                    if (bv > thr) {
                        int bc = ct * 128 + 32 * j + ld;
                        unsigned gt = __ballot_sync(FULL, tv[rr] > bv);
                        int pos = __popc(gt);
                        float pv = __shfl_up_sync(FULL, tv[rr], 1);
                        int   pi = __shfl_up_sync(FULL, ti[rr], 1);
                        if (lane == pos)      { tv[rr] = bv; ti[rr] = bc; }
                        else if (lane > pos)  { tv[rr] = pv; ti[rr] = pi; }
                        thr = __shfl_sync(FULL, tv[rr], 31);
                    }
                }
            }
        }
    }
    __syncthreads();

    // ---- exact fp32 rescore + quantiles: warp per row, 8 rows ----
#pragma unroll
    for (int rr = 0; rr < 8; rr++) {
        const int r = wid * 8 + rr;
        const int sgl = rt0 + r;                        // s index in [0,2048)
        // stage q fp32 row for broadcast
        const float* qrow = qk + ((size_t)(b * SS + sgl)) * (HH * DD) + h * DD;
        *reinterpret_cast<float4*>(&qf[wid * 128 + lane * 4]) =
            *reinterpret_cast<const float4*>(qrow + lane * 4);
        __syncwarp();

        const int my_m = ti[rr];
        const float* krow = qk + KOFF + ((size_t)(b * SS + my_m)) * (HH * DD) + h * DD;
        float ex = 0.f;
#pragma unroll
        for (int d4 = 0; d4 < 32; d4++) {
            float4 kv = *reinterpret_cast<const float4*>(krow + d4 * 4);
            float4 qv = *reinterpret_cast<const float4*>(&qf[wid * 128 + d4 * 4]);
            ex = fmaf(qv.x, kv.x, ex);
            ex = fmaf(qv.y, kv.y, ex);
            ex = fmaf(qv.z, kv.z, ex);
            ex = fmaf(qv.w, kv.w, ex);
        }

        // rank among 32 by (exact score desc, index asc)
        int rank_sel = 0;
#pragma unroll
        for (int j = 0; j < NSEL; j++) {
            float sj = __shfl_sync(FULL, ex, j);
            int   mj = __shfl_sync(FULL, my_m, j);
            if ((sj > ex) || (sj == ex && mj < my_m)) rank_sel++;
        }
        const bool selected = (rank_sel < KK);

        float e = selected ? errors[((size_t)(b * SS + my_m)) * 4 + 0] : 0.f;

        // sort the 20 selected error values (ascending)
        int rank_e = 0;
#pragma unroll
        for (int j = 0; j < NSEL; j++) {
            float ej  = __shfl_sync(FULL, e, j);
            int   rsj = __shfl_sync(FULL, rank_sel, j);
            if (selected && rsj < KK && ((ej < e) || (ej == e && rsj < rank_sel))) rank_e++;
        }
        if (selected) srt[wid * KK + rank_e] = e;
        __syncwarp();

        const float yp = y_pred[((size_t)(b * SS + sgl)) * 4 + 0];
        float ql = 0.f, qh = 0.f;
        if (lane < NA) {
            float alpha = c_alphas[lane];
            float pl = 0.5f * alpha * (float)(KK - 1);
            int il = (int)pl; float fl = pl - (float)il;
            ql = srt[wid * KK + il] + fl * (srt[wid * KK + il + 1] - srt[wid * KK + il]);
            float ph = (1.f - 0.5f * alpha) * (float)(KK - 1);
            int ih = (int)ph; float fh = ph - (float)ih;
            qh = srt[wid * KK + ih] + fh * (srt[wid * KK + ih + 1] - srt[wid * KK + ih]);
            size_t oidx = ((size_t)((h * BB + b) * NA + lane)) * SS + sgl;
            out[OFF_QLOW  + oidx] = ql;
            out[OFF_QHIGH + oidx] = qh;
            out[OFF_YLOW  + oidx] = ql + yp;
            out[OFF_YHIGH + oidx] = qh + yp;
        }

        float t = ql + qh;
#pragma unroll
        for (int o = 16; o; o >>= 1) t += __shfl_down_sync(FULL, t, o);
        if (lane == 0) {
            float me = t * (1.f / 36.f);
            float yt = y[((size_t)(b * SS + sgl)) * 4 + 0];
            float d = yt - (me + yp);
            g_rowsq[(size_t)(b * HH + h) * SS + sgl] = d * d;
        }
        __syncwarp();   // srt reused next row
    }
}

// ---------------- LayerNorm (warp per row) ----------------
__global__ __launch_bounds__(256) void ln_kernel(
    const float* __restrict__ gq, const float* __restrict__ bq,
    const float* __restrict__ gk, const float* __restrict__ bk)
{
    const int warp = threadIdx.x >> 5, lane = threadIdx.x & 31;
    const int row = blockIdx.x * 8 + warp;
    const float* x = g_enc + (size_t)row * DD;
    float v0 = x[lane], v1 = x[lane + 32], v2 = x[lane + 64], v3 = x[lane + 96];
    float s = v0 + v1 + v2 + v3;
#pragma unroll
    for (int o = 16; o; o >>= 1) s += __shfl_xor_sync(0xffffffffu, s, o);
    float mu = s * (1.f / 128.f);
    float d0 = v0 - mu, d1 = v1 - mu, d2 = v2 - mu, d3 = v3 - mu;
    float sq = d0 * d0 + d1 * d1 + d2 * d2 + d3 * d3;
#pragma unroll
    for (int o = 16; o; o >>= 1) sq += __shfl_xor_sync(0xffffffffu, sq, o);
    float rs = rsqrtf(sq * (1.f / 128.f) + 1e-5f);
    const float* g = (row < NTOK) ? gq : gk;
    const float* be = (row < NTOK) ? bq : bk;
    float* o = g_ln + (size_t)row * DD;
    o[lane]      = d0 * rs * g[lane]      + be[lane];
    o[lane + 32] = d1 * rs * g[lane + 32] + be[lane + 32];
    o[lane + 64] = d2 * rs * g[lane + 64] + be[lane + 64];
    o[lane + 96] = d3 * rs * g[lane + 96] + be[lane + 96];
}

// ---------------- passthrough copies ----------------
__global__ void copy_kernel(const float* __restrict__ y,
                            const float* __restrict__ yp,
                            const float* __restrict__ err,
                            float* __restrict__ out)
{
    int i = blockIdx.x * blockDim.x + threadIdx.x;
    if (i < 32768) out[OFF_Y + i] = y[i];
    else if (i < 65536) out[OFF_YPRED + (i - 32768)] = yp[i - 32768];
    else if (i < 73728) { int j = i - 65536; out[OFF_ERR + j] = err[(size_t)j * 4]; }
}

// ---------------- final scalar reduce ----------------
__global__ void reduce_kernel(float* __restrict__ out)
{
    __shared__ float sh[1024];
    float s = 0.f;
    for (int i = threadIdx.x; i < NROW; i += 1024) s += g_rowsq[i];
    sh[threadIdx.x] = s;
    __syncthreads();
    for (int o = 512; o; o >>= 1) {
        if (threadIdx.x < o) sh[threadIdx.x] += sh[threadIdx.x + o];
        __syncthreads();
    }
    if (threadIdx.x == 0) out[OFF_SCORE] = sh[0] * (1.f / (float)NROW);
}

// ---------------- launch ----------------
extern "C" void kernel_launch(void* const* d_in, const int* in_sizes, int n_in,
                              void* d_out, int out_size)
{
    const float* Xt   = (const float*)d_in[0];
    const float* Xs   = (const float*)d_in[1];
    const float* err  = (const float*)d_in[2];
    const float* y    = (const float*)d_in[3];
    const float* ypr  = (const float*)d_in[4];
    const float* W1   = (const float*)d_in[5];
    const float* b1   = (const float*)d_in[6];
    const float* W2   = (const float*)d_in[7];
    const float* b2   = (const float*)d_in[8];
    const float* W3   = (const float*)d_in[9];
    const float* b3   = (const float*)d_in[10];
    const float* W4   = (const float*)d_in[11];
    const float* b4   = (const float*)d_in[12];
    const float* Wq   = (const float*)d_in[13];
    const float* bq   = (const float*)d_in[14];
    const float* Wk   = (const float*)d_in[15];
    const float* bk   = (const float*)d_in[16];
    const float* gq   = (const float*)d_in[17];
    const float* betaq= (const float*)d_in[18];
    const float* gk   = (const float*)d_in[19];
    const float* betak= (const float*)d_in[20];
    float* out = (float*)d_out;

    float *p_h1, *p_h2, *p_enc, *p_ln, *p_qk;
    cudaGetSymbolAddress((void**)&p_h1, g_h1);
    cudaGetSymbolAddress((void**)&p_h2, g_h2);
    cudaGetSymbolAddress((void**)&p_enc, g_enc);
    cudaGetSymbolAddress((void**)&p_ln, g_ln);
    cudaGetSymbolAddress((void**)&p_qk, g_qk);

    cudaFuncSetAttribute(fused_scores_topk,
                         cudaFuncAttributeMaxDynamicSharedMemorySize, SM_FUSED_TOTAL);

    // MLP layer 1 (true rows [0,8192), sim rows [8192,16384))
    sgemm_bias<<<dim3(4, 64), 256>>>(Xt, INF_DIM, W1, HID, b1, p_h1, HID, HID, INF_DIM, 1);
    sgemm_bias<<<dim3(4, 64), 256>>>(Xs, INF_DIM, W1, HID, b1, p_h1 + (size_t)NTOK * HID, HID, HID, INF_DIM, 1);
    // layers 2,3
    sgemm_bias<<<dim3(4, 128), 256>>>(p_h1, HID, W2, HID, b2, p_h2, HID, HID, HID, 1);
    sgemm_bias<<<dim3(4, 128), 256>>>(p_h2, HID, W3, HID, b3, p_h1, HID, HID, HID, 1);
    // layer 4 (no relu) -> enc
    sgemm_bias<<<dim3(1, 128), 256>>>(p_h1, HID, W4, DD, b4, p_enc, DD, DD, HID, 0);
    // layernorm
    ln_kernel<<<NTOK2 / 8, 256>>>(gq, betaq, gk, betak);
    // projections
    sgemm_bias<<<dim3(4, 64), 256>>>(p_ln, DD, Wq, HH * DD, bq, p_qk, HH * DD, HH * DD, DD, 0);
    sgemm_bias<<<dim3(4, 64), 256>>>(p_ln + (size_t)NTOK * DD, DD, Wk, HH * DD, bk,
                                     p_qk + KOFF, HH * DD, HH * DD, DD, 0);
    // bf16 conversion for tensor-core scores
    cvt_bf16_kernel<<<4096, 256>>>(p_qk);
    // fused: scores MMA + register top-32 + exact fp32 rescore + quantiles
    fused_scores_topk<<<dim3(32, 16), 256, SM_FUSED_TOTAL>>>(p_qk, err, y, ypr, out);
    // passthrough copies
    copy_kernel<<<288, 256>>>(y, ypr, err, out);
    // scalar score
    reduce_kernel<<<1, 1024>>>(out);
}

// round 14
// speedup vs baseline: 2.6050x; 1.0055x over previous
#include <cuda_runtime.h>
#include <cuda_bf16.h>
#include <math.h>
#include <stdint.h>

// ---------------- problem constants ----------------
#define BB 4
#define SS 2048
#define INF_DIM 64
#define DD 128
#define HID 400
#define HH 4
#define KK 20
#define NSEL 32
#define NA 18

#define NTOK 8192          // B*S
#define NTOK2 16384        // 2*B*S (true + sim)
#define NROW 32768         // B*H*S
#define KOFF ((size_t)NTOK * (HH * DD))   // offset of k rows inside g_qk

// output offsets (flattened tuple, C-order concat)
#define OFF_SCORE 0
#define OFF_Y     1
#define OFF_YPRED 32769
#define OFF_YLOW  65537
#define OFF_YHIGH 655361
#define OFF_ERR   1245185
#define OFF_QLOW  1253377
#define OFF_QHIGH 1843201
// total 2433025

__constant__ float c_alphas[NA] = {0.05f,0.06f,0.08f,0.1f,0.12f,0.14f,0.15f,0.17f,0.19f,
                                   0.2f,0.21f,0.23f,0.25f,0.3f,0.35f,0.38f,0.4f,0.45f};

// ---------------- scratch (static device allocations) ----------------
__device__ float g_h1[NTOK2 * HID];
__device__ float g_h2[NTOK2 * HID];
__device__ float g_enc[NTOK2 * DD];
__device__ float g_ln[NTOK2 * DD];
__device__ float g_qk[NTOK2 * (HH * DD)];
__device__ __nv_bfloat16 g_qb[(size_t)BB * HH * SS * DD];   // [bh][s][d]
__device__ __nv_bfloat16 g_kb[(size_t)BB * HH * SS * DD];
__device__ float g_rowsq[NROW];

// ---------------- packed f32x2 helpers (sm_100+ PTX, compute_103-safe) --------
#define PACK2(d, x, y) \
    asm("mov.b64 %0, {%1, %2};" : "=l"(d) : "f"(x), "f"(y))
#define UNPACK2(x, y, d) \
    asm("mov.b64 {%0, %1}, %2;" : "=f"(x), "=f"(y) : "l"(d))
#define FMA2(acc, aa, ww) \
    asm("fma.rn.f32x2 %0, %1, %2, %0;" : "+l"(acc) : "l"(aa), "l"(ww))

// ---------------- mma.sync helpers (compute_103-safe, sm_80 era PTX) ----------
__device__ __forceinline__ uint32_t smem_u32(const void* p) {
    uint32_t a;
    asm("{ .reg .u64 t; cvta.to.shared.u64 t, %1; cvt.u32.u64 %0, t; }" : "=r"(a) : "l"(p));
    return a;
}
__device__ __forceinline__ void ldsm_x4(uint32_t& r0, uint32_t& r1, uint32_t& r2, uint32_t& r3,
                                        uint32_t addr) {
    asm volatile("ldmatrix.sync.aligned.m8n8.x4.shared.b16 {%0,%1,%2,%3}, [%4];"
                 : "=r"(r0), "=r"(r1), "=r"(r2), "=r"(r3) : "r"(addr));
}
__device__ __forceinline__ void mma_bf16(float* c, const uint32_t* a, const uint32_t* b) {
    asm volatile("mma.sync.aligned.m16n8k16.row.col.f32.bf16.bf16.f32 "
                 "{%0,%1,%2,%3}, {%4,%5,%6,%7}, {%8,%9}, {%0,%1,%2,%3};"
                 : "+f"(c[0]), "+f"(c[1]), "+f"(c[2]), "+f"(c[3])
                 : "r"(a[0]), "r"(a[1]), "r"(a[2]), "r"(a[3]), "r"(b[0]), "r"(b[1]));
}

// swizzled offset within a tile: row stride 256B, 16 chunks of 16B,
// XOR swizzle applied within each 128B half -> ldmatrix conflict-free.
__device__ __forceinline__ uint32_t tile_swz(int row, int ch) {
    return (uint32_t)row * 256u +
           (uint32_t)(((ch & 8) | ((ch ^ (row & 7)) & 7)) << 4);
}

// ---------------- generic SGEMM: C = act(A @ W + bias) (fp32, f32x2 FMA) ------
__global__ __launch_bounds__(256) void sgemm_bias(
    const float* __restrict__ A, int lda,
    const float* __restrict__ W, int ldw,
    const float* __restrict__ bias,
    float* __restrict__ C, int ldc,
    int N, int K, int relu)
{
    __shared__ float As[2][8][128];
    __shared__ float Ws[2][8][128];
    const int tid = threadIdx.x;
    const int row0 = blockIdx.y * 128;
    const int col0 = blockIdx.x * 128;
    const int m0 = (tid >> 4) << 3;
    const int n0 = (tid & 15) << 3;
    const int ar = tid >> 1;
    const int ac = (tid & 1) << 2;
    const int wr = tid >> 5;
    const int wc = (tid & 31) << 2;
    const bool fullN = (col0 + 128 <= N);

    const float* Ap = A + (size_t)(row0 + ar) * lda + ac;

    // packed accumulators: accp[i][p] = (acc[i][2p], acc[i][2p+1])
    uint64_t accp[8][4];
#pragma unroll
    for (int i = 0; i < 8; i++)
#pragma unroll
        for (int p = 0; p < 4; p++) PACK2(accp[i][p], 0.f, 0.f);

    const int nk = K >> 3;
    float4 av = *reinterpret_cast<const float4*>(Ap);
    float4 wv;
    {
        const float* wp = W + (size_t)wr * ldw + col0 + wc;
        if (fullN) wv = *reinterpret_cast<const float4*>(wp);
        else {
            wv.x = (col0 + wc + 0 < N) ? wp[0] : 0.f;
            wv.y = (col0 + wc + 1 < N) ? wp[1] : 0.f;
            wv.z = (col0 + wc + 2 < N) ? wp[2] : 0.f;
            wv.w = (col0 + wc + 3 < N) ? wp[3] : 0.f;
        }
    }
    As[0][ac + 0][ar] = av.x; As[0][ac + 1][ar] = av.y;
    As[0][ac + 2][ar] = av.z; As[0][ac + 3][ar] = av.w;
    *reinterpret_cast<float4*>(&Ws[0][wr][wc]) = wv;
    __syncthreads();

    int buf = 0;
    for (int t = 0; t < nk; t++) {
        const bool more = (t + 1 < nk);
        if (more) {
            const int k0 = (t + 1) << 3;
            av = *reinterpret_cast<const float4*>(Ap + k0);
            const float* wp = W + (size_t)(k0 + wr) * ldw + col0 + wc;
            if (fullN) wv = *reinterpret_cast<const float4*>(wp);
            else {
                wv.x = (col0 + wc + 0 < N) ? wp[0] : 0.f;
                wv.y = (col0 + wc + 1 < N) ? wp[1] : 0.f;
                wv.z = (col0 + wc + 2 < N) ? wp[2] : 0.f;
                wv.w = (col0 + wc + 3 < N) ? wp[3] : 0.f;
            }
        }
#pragma unroll
        for (int kk = 0; kk < 8; kk++) {
            float4 a0 = *reinterpret_cast<const float4*>(&As[buf][kk][m0]);
            float4 a1 = *reinterpret_cast<const float4*>(&As[buf][kk][m0 + 4]);
            float4 w0 = *reinterpret_cast<const float4*>(&Ws[buf][kk][n0]);
            float4 w1 = *reinterpret_cast<const float4*>(&Ws[buf][kk][n0 + 4]);
            float a[8] = {a0.x, a0.y, a0.z, a0.w, a1.x, a1.y, a1.z, a1.w};
            uint64_t wp2[4];
            PACK2(wp2[0], w0.x, w0.y);
            PACK2(wp2[1], w0.z, w0.w);
            PACK2(wp2[2], w1.x, w1.y);
            PACK2(wp2[3], w1.z, w1.w);
#pragma unroll
            for (int i = 0; i < 8; i++) {
                uint64_t aa;
                PACK2(aa, a[i], a[i]);
#pragma unroll
                for (int p = 0; p < 4; p++) FMA2(accp[i][p], aa, wp2[p]);
            }
        }
        if (more) {
            const int nb = buf ^ 1;
            As[nb][ac + 0][ar] = av.x; As[nb][ac + 1][ar] = av.y;
            As[nb][ac + 2][ar] = av.z; As[nb][ac + 3][ar] = av.w;
            *reinterpret_cast<float4*>(&Ws[nb][wr][wc]) = wv;
            __syncthreads();
            buf = nb;
        }
    }

    // unpack accumulators
    float acc[8][8];
#pragma unroll
    for (int i = 0; i < 8; i++)
#pragma unroll
        for (int p = 0; p < 4; p++)
            UNPACK2(acc[i][2 * p], acc[i][2 * p + 1], accp[i][p]);

#pragma unroll
    for (int j = 0; j < 8; j++) {
        int c = col0 + n0 + j;
        if (c < N) {
            float bb = bias[c];
#pragma unroll
            for (int i = 0; i < 8; i++) {
                float v = acc[i][j] + bb;
                if (relu) v = fmaxf(v, 0.f);
                C[(size_t)(row0 + m0 + i) * ldc + c] = v;
            }
        }
    }
}

// ---------------- fp32 -> bf16 conversion, [b,s,h,d] -> [bh][s][d] ------------
__global__ __launch_bounds__(256) void cvt_bf16_kernel(const float* __restrict__ qk)
{
    int idx = blockIdx.x * 256 + threadIdx.x;     // < 1048576 (float4 groups)
    int d4 = idx & 31;
    int s  = (idx >> 5) & 2047;
    int bh = idx >> 16;
    int b = bh >> 2, h = bh & 3;
    size_t src = ((size_t)(b * SS + s)) * (HH * DD) + h * DD + d4 * 4;
    float4 q = *reinterpret_cast<const float4*>(qk + src);
    float4 k = *reinterpret_cast<const float4*>(qk + KOFF + src);
    __nv_bfloat162 q01 = __floats2bfloat162_rn(q.x, q.y);
    __nv_bfloat162 q23 = __floats2bfloat162_rn(q.z, q.w);
    __nv_bfloat162 k01 = __floats2bfloat162_rn(k.x, k.y);
    __nv_bfloat162 k23 = __floats2bfloat162_rn(k.z, k.w);
    uint2* qd = reinterpret_cast<uint2*>(g_qb) + idx;
    uint2* kd = reinterpret_cast<uint2*>(g_kb) + idx;
    *qd = make_uint2(*(uint32_t*)&q01, *(uint32_t*)&q23);
    *kd = make_uint2(*(uint32_t*)&k01, *(uint32_t*)&k23);
}

// ---------------- fused scores MMA + top-32 + exact rescore + quantiles -------
// grid (32 row-tiles of 64, 16 bh), 256 threads (8 warps, warp tile 16x64).
// 2 CTAs/SM (smem 87.7KB) -> phases of co-resident CTAs overlap.
// Top-32 list in registers distributed across each warp (lane l = rank l).
// smem layout (dynamic):
#define SM_QT   0          // Q bf16 tile 64x128, 16384 B (swizzled, 256B row stride)
#define SM_KT   16384      // K bf16 tile 128x128, 32768 B
#define SM_SC   49152      // scores f32 [64][132] = 33792 B
#define SM_QF   82944      // per-warp q fp32 row [8][128] = 4096 B
#define SM_SRT  87040      // per-warp sorted errs [8][20] = 640 B
#define SM_FUSED_TOTAL 87680

__global__ __launch_bounds__(256, 2) void fused_scores_topk(
    const float* __restrict__ qk,
    const float* __restrict__ errors,
    const float* __restrict__ y,
    const float* __restrict__ y_pred,
    float* __restrict__ out)
{
    extern __shared__ char smem[];
    const uint32_t sb = smem_u32(smem);
    float* sc  = reinterpret_cast<float*>(smem + SM_SC);
    float* qf  = reinterpret_cast<float*>(smem + SM_QF);
    float* srt = reinterpret_cast<float*>(smem + SM_SRT);

    const int tid = threadIdx.x;
    const int wid = tid >> 5, lane = tid & 31;
    const int rt0 = blockIdx.x * 64;      // q row tile base
    const int bh = blockIdx.y;
    const int b = bh >> 2, h = bh & 3;
    const float ninf = __int_as_float(0xff800000);
    const unsigned FULL = 0xffffffffu;

    // distributed-register top-32 lists: lane l = rank l, per row rr (8 rows/warp)
    float tv[8];
    int   ti[8];
#pragma unroll
    for (int rr = 0; rr < 8; rr++) { tv[rr] = ninf; ti[rr] = 0; }

    // load Q tile 64x128 (swizzled): 1024 chunks
    const __nv_bfloat16* qsrc = g_qb + ((size_t)bh * SS + rt0) * DD;
#pragma unroll
    for (int i = 0; i < 4; i++) {
        int idx = tid + i * 256;          // 0..1023
        int row = idx >> 4, ch = idx & 15;
        *reinterpret_cast<uint4*>(smem + SM_QT + tile_swz(row, ch)) =
            *reinterpret_cast<const uint4*>(qsrc + (size_t)row * DD + ch * 8);
    }

    const int wm0 = (wid & 3) * 16;       // 4 m-warps (16 rows each)
    const int wn0 = (wid >> 2) * 64;      // 2 n-warps (64 cols each)

    // A fragment base (single m-fragment of 16 rows)
    uint32_t abase; int ax;
    {
        int r = wm0 + (lane & 15);
        abase = sb + SM_QT + (uint32_t)r * 256u;
        ax = r & 7;
    }
    const int alb = lane >> 4;
    // B fragment bases: 4 x (16-col pair fragments)
    uint32_t bbase[4]; int bx[4];
#pragma unroll
    for (int nf2 = 0; nf2 < 4; nf2++) {
        int r = wn0 + nf2 * 16 + (lane & 7) + ((lane & 16) >> 1);
        bbase[nf2] = sb + SM_KT + (uint32_t)r * 256u;
        bx[nf2] = r & 7;
    }
    const int blb = (lane >> 3) & 1;

    const float scale = 0.08838834764831845f;   // 1/sqrt(128)

    for (int ct = 0; ct < 16; ct++) {
        __syncthreads();   // sc/Kt consumed by previous iteration
        // load K tile 128x128 (rows ct*128..+127): 2048 chunks
        const __nv_bfloat16* ksrc = g_kb + ((size_t)bh * SS + ct * 128) * DD;
#pragma unroll
        for (int i = 0; i < 8; i++) {
            int idx = tid + i * 256;
            int row = idx >> 4, ch = idx & 15;
            *reinterpret_cast<uint4*>(smem + SM_KT + tile_swz(row, ch)) =
                *reinterpret_cast<const uint4*>(ksrc + (size_t)row * DD + ch * 8);
        }
        __syncthreads();

        float acc[8][4];
#pragma unroll
        for (int nf = 0; nf < 8; nf++)
#pragma unroll
            for (int i = 0; i < 4; i++) acc[nf][i] = 0.f;

#pragma unroll
        for (int s = 0; s < 8; s++) {
            uint32_t a[4], bfr[8][2];
            const int ca = 2 * s + alb;
            const int cb = 2 * s + blb;
            ldsm_x4(a[0], a[1], a[2], a[3],
                    abase + (uint32_t)(((ca & 8) | ((ca ^ ax) & 7)) << 4));
#pragma unroll
            for (int nf2 = 0; nf2 < 4; nf2++) {
                uint32_t r0, r1, r2, r3;
                ldsm_x4(r0, r1, r2, r3,
                        bbase[nf2] + (uint32_t)(((cb & 8) | ((cb ^ bx[nf2]) & 7)) << 4));
                bfr[nf2 * 2][0] = r0; bfr[nf2 * 2][1] = r1;
                bfr[nf2 * 2 + 1][0] = r2; bfr[nf2 * 2 + 1][1] = r3;
            }
#pragma unroll
            for (int nf = 0; nf < 8; nf++)
                mma_bf16(acc[nf], a, bfr[nf]);
        }

        // epilogue: scaled scores (diag-masked) -> smem sc
        const int qr = lane >> 2, qc = (lane & 3) * 2;
        {
            int r1 = wm0 + qr;
            int r2 = r1 + 8;
            int gr1 = rt0 + r1, gr2 = rt0 + r2;
#pragma unroll
            for (int nf = 0; nf < 8; nf++) {
                int cl = wn0 + nf * 8 + qc;
                int gc = ct * 128 + cl;
                float2 v1, v2;
                v1.x = (gr1 == gc)     ? ninf : acc[nf][0] * scale;
                v1.y = (gr1 == gc + 1) ? ninf : acc[nf][1] * scale;
                v2.x = (gr2 == gc)     ? ninf : acc[nf][2] * scale;
                v2.y = (gr2 == gc + 1) ? ninf : acc[nf][3] * scale;
                *reinterpret_cast<float2*>(&sc[r1 * 132 + cl]) = v1;
                *reinterpret_cast<float2*>(&sc[r2 * 132 + cl]) = v2;
            }
        }
        __syncthreads();

        // top-32 streaming update, warp-parallel register insertion.
        // warp handles rows wid*8 .. wid*8+7
#pragma unroll
        for (int rr = 0; rr < 8; rr++) {
            const int r = wid * 8 + rr;
            float thr = __shfl_sync(FULL, tv[rr], 31);
#pragma unroll
            for (int j = 0; j < 4; j++) {
                float x = sc[r * 132 + lane + 32 * j];
                unsigned m = __ballot_sync(FULL, x > thr);
                while (m) {
                    int ld = __ffs(m) - 1; m &= m - 1;
                    float bv = __shfl_sync(FULL, x, ld);
                    if (bv > thr) {
                        int bc = ct * 128 + 32 * j + ld;
                        unsigned gt = __ballot_sync(FULL, tv[rr] > bv);
                        int pos = __popc(gt);
                        float pv = __shfl_up_sync(FULL, tv[rr], 1);
                        int   pi = __shfl_up_sync(FULL, ti[rr], 1);
                        if (lane == pos)      { tv[rr] = bv; ti[rr] = bc; }
                        else if (lane > pos)  { tv[rr] = pv; ti[rr] = pi; }
                        thr = __shfl_sync(FULL, tv[rr], 31);
                    }
                }
            }
        }
    }
    __syncthreads();

    // ---- exact fp32 rescore + quantiles: warp per row, 8 rows ----
#pragma unroll
    for (int rr = 0; rr < 8; rr++) {
        const int r = wid * 8 + rr;
        const int sgl = rt0 + r;                        // s index in [0,2048)
        // stage q fp32 row for broadcast
        const float* qrow = qk + ((size_t)(b * SS + sgl)) * (HH * DD) + h * DD;
        *reinterpret_cast<float4*>(&qf[wid * 128 + lane * 4]) =
            *reinterpret_cast<const float4*>(qrow + lane * 4);
        __syncwarp();

        const int my_m = ti[rr];
        const float* krow = qk + KOFF + ((size_t)(b * SS + my_m)) * (HH * DD) + h * DD;
        float ex = 0.f;
#pragma unroll
        for (int d4 = 0; d4 < 32; d4++) {
            float4 kv = *reinterpret_cast<const float4*>(krow + d4 * 4);
            float4 qv = *reinterpret_cast<const float4*>(&qf[wid * 128 + d4 * 4]);
            ex = fmaf(qv.x, kv.x, ex);
            ex = fmaf(qv.y, kv.y, ex);
            ex = fmaf(qv.z, kv.z, ex);
            ex = fmaf(qv.w, kv.w, ex);
        }

        // rank among 32 by (exact score desc, index asc)
        int rank_sel = 0;
#pragma unroll
        for (int j = 0; j < NSEL; j++) {
            float sj = __shfl_sync(FULL, ex, j);
            int   mj = __shfl_sync(FULL, my_m, j);
            if ((sj > ex) || (sj == ex && mj < my_m)) rank_sel++;
        }
        const bool selected = (rank_sel < KK);

        float e = selected ? errors[((size_t)(b * SS + my_m)) * 4 + 0] : 0.f;

        // sort the 20 selected error values (ascending)
        int rank_e = 0;
#pragma unroll
        for (int j = 0; j < NSEL; j++) {
            float ej  = __shfl_sync(FULL, e, j);
            int   rsj = __shfl_sync(FULL, rank_sel, j);
            if (selected && rsj < KK && ((ej < e) || (ej == e && rsj < rank_sel))) rank_e++;
        }
        if (selected) srt[wid * KK + rank_e] = e;
        __syncwarp();

        const float yp = y_pred[((size_t)(b * SS + sgl)) * 4 + 0];
        float ql = 0.f, qh = 0.f;
        if (lane < NA) {
            float alpha = c_alphas[lane];
            float pl = 0.5f * alpha * (float)(KK - 1);
            int il = (int)pl; float fl = pl - (float)il;
            ql = srt[wid * KK + il] + fl * (srt[wid * KK + il + 1] - srt[wid * KK + il]);
            float ph = (1.f - 0.5f * alpha) * (float)(KK - 1);
            int ih = (int)ph; float fh = ph - (float)ih;
            qh = srt[wid * KK + ih] + fh * (srt[wid * KK + ih + 1] - srt[wid * KK + ih]);
            size_t oidx = ((size_t)((h * BB + b) * NA + lane)) * SS + sgl;
            out[OFF_QLOW  + oidx] = ql;
            out[OFF_QHIGH + oidx] = qh;
            out[OFF_YLOW  + oidx] = ql + yp;
            out[OFF_YHIGH + oidx] = qh + yp;
        }

        float t = ql + qh;
#pragma unroll
        for (int o = 16; o; o >>= 1) t += __shfl_down_sync(FULL, t, o);
        if (lane == 0) {
            float me = t * (1.f / 36.f);
            float yt = y[((size_t)(b * SS + sgl)) * 4 + 0];
            float d = yt - (me + yp);
            g_rowsq[(size_t)(b * HH + h) * SS + sgl] = d * d;
        }
        __syncwarp();   // srt reused next row
    }
}

// ---------------- LayerNorm (warp per row) ----------------
__global__ __launch_bounds__(256) void ln_kernel(
    const float* __restrict__ gq, const float* __restrict__ bq,
    const float* __restrict__ gk, const float* __restrict__ bk)
{
    const int warp = threadIdx.x >> 5, lane = threadIdx.x & 31;
    const int row = blockIdx.x * 8 + warp;
    const float* x = g_enc + (size_t)row * DD;
    float v0 = x[lane], v1 = x[lane + 32], v2 = x[lane + 64], v3 = x[lane + 96];
    float s = v0 + v1 + v2 + v3;
#pragma unroll
    for (int o = 16; o; o >>= 1) s += __shfl_xor_sync(0xffffffffu, s, o);
    float mu = s * (1.f / 128.f);
    float d0 = v0 - mu, d1 = v1 - mu, d2 = v2 - mu, d3 = v3 - mu;
    float sq = d0 * d0 + d1 * d1 + d2 * d2 + d3 * d3;
#pragma unroll
    for (int o = 16; o; o >>= 1) sq += __shfl_xor_sync(0xffffffffu, sq, o);
    float rs = rsqrtf(sq * (1.f / 128.f) + 1e-5f);
    const float* g = (row < NTOK) ? gq : gk;
    const float* be = (row < NTOK) ? bq : bk;
    float* o = g_ln + (size_t)row * DD;
    o[lane]      = d0 * rs * g[lane]      + be[lane];
    o[lane + 32] = d1 * rs * g[lane + 32] + be[lane + 32];
    o[lane + 64] = d2 * rs * g[lane + 64] + be[lane + 64];
    o[lane + 96] = d3 * rs * g[lane + 96] + be[lane + 96];
}

// ---------------- passthrough copies ----------------
__global__ void copy_kernel(const float* __restrict__ y,
                            const float* __restrict__ yp,
                            const float* __restrict__ err,
                            float* __restrict__ out)
{
    int i = blockIdx.x * blockDim.x + threadIdx.x;
    if (i < 32768) out[OFF_Y + i] = y[i];
    else if (i < 65536) out[OFF_YPRED + (i - 32768)] = yp[i - 32768];
    else if (i < 73728) { int j = i - 65536; out[OFF_ERR + j] = err[(size_t)j * 4]; }
}

// ---------------- final scalar reduce ----------------
__global__ void reduce_kernel(float* __restrict__ out)
{
    __shared__ float sh[1024];
    float s = 0.f;
    for (int i = threadIdx.x; i < NROW; i += 1024) s += g_rowsq[i];
    sh[threadIdx.x] = s;
    __syncthreads();
    for (int o = 512; o; o >>= 1) {
        if (threadIdx.x < o) sh[threadIdx.x] += sh[threadIdx.x + o];
        __syncthreads();
    }
    if (threadIdx.x == 0) out[OFF_SCORE] = sh[0] * (1.f / (float)NROW);
}

// ---------------- launch ----------------
extern "C" void kernel_launch(void* const* d_in, const int* in_sizes, int n_in,
                              void* d_out, int out_size)
{
    const float* Xt   = (const float*)d_in[0];
    const float* Xs   = (const float*)d_in[1];
    const float* err  = (const float*)d_in[2];
    const float* y    = (const float*)d_in[3];
    const float* ypr  = (const float*)d_in[4];
    const float* W1   = (const float*)d_in[5];
    const float* b1   = (const float*)d_in[6];
    const float* W2   = (const float*)d_in[7];
    const float* b2   = (const float*)d_in[8];
    const float* W3   = (const float*)d_in[9];
    const float* b3   = (const float*)d_in[10];
    const float* W4   = (const float*)d_in[11];
    const float* b4   = (const float*)d_in[12];
    const float* Wq   = (const float*)d_in[13];
    const float* bq   = (const float*)d_in[14];
    const float* Wk   = (const float*)d_in[15];
    const float* bk   = (const float*)d_in[16];
    const float* gq   = (const float*)d_in[17];
    const float* betaq= (const float*)d_in[18];
    const float* gk   = (const float*)d_in[19];
    const float* betak= (const float*)d_in[20];
    float* out = (float*)d_out;

    float *p_h1, *p_h2, *p_enc, *p_ln, *p_qk;
    cudaGetSymbolAddress((void**)&p_h1, g_h1);
    cudaGetSymbolAddress((void**)&p_h2, g_h2);
    cudaGetSymbolAddress((void**)&p_enc, g_enc);
    cudaGetSymbolAddress((void**)&p_ln, g_ln);
    cudaGetSymbolAddress((void**)&p_qk, g_qk);

    cudaFuncSetAttribute(fused_scores_topk,
                         cudaFuncAttributeMaxDynamicSharedMemorySize, SM_FUSED_TOTAL);

    // MLP layer 1 (true rows [0,8192), sim rows [8192,16384))
    sgemm_bias<<<dim3(4, 64), 256>>>(Xt, INF_DIM, W1, HID, b1, p_h1, HID, HID, INF_DIM, 1);
    sgemm_bias<<<dim3(4, 64), 256>>>(Xs, INF_DIM, W1, HID, b1, p_h1 + (size_t)NTOK * HID, HID, HID, INF_DIM, 1);
    // layers 2,3
    sgemm_bias<<<dim3(4, 128), 256>>>(p_h1, HID, W2, HID, b2, p_h2, HID, HID, HID, 1);
    sgemm_bias<<<dim3(4, 128), 256>>>(p_h2, HID, W3, HID, b3, p_h1, HID, HID, HID, 1);
    // layer 4 (no relu) -> enc
    sgemm_bias<<<dim3(1, 128), 256>>>(p_h1, HID, W4, DD, b4, p_enc, DD, DD, HID, 0);
    // layernorm
    ln_kernel<<<NTOK2 / 8, 256>>>(gq, betaq, gk, betak);
    // projections
    sgemm_bias<<<dim3(4, 64), 256>>>(p_ln, DD, Wq, HH * DD, bq, p_qk, HH * DD, HH * DD, DD, 0);
    sgemm_bias<<<dim3(4, 64), 256>>>(p_ln + (size_t)NTOK * DD, DD, Wk, HH * DD, bk,
                                     p_qk + KOFF, HH * DD, HH * DD, DD, 0);
    // bf16 conversion for tensor-core scores
    cvt_bf16_kernel<<<4096, 256>>>(p_qk);
    // fused: scores MMA + register top-32 + exact fp32 rescore + quantiles
    fused_scores_topk<<<dim3(32, 16), 256, SM_FUSED_TOTAL>>>(p_qk, err, y, ypr, out);
    // passthrough copies
    copy_kernel<<<288, 256>>>(y, ypr, err, out);
    // scalar score
    reduce_kernel<<<1, 1024>>>(out);
}